// round 13
// baseline (speedup 1.0000x reference)
#include <cuda_runtime.h>
#include <cstdint>

#define BB 4
#define CC 256
#define CI 128
#define TT 8192
#define NN 4096
#define BNT (BB*TT)

// Scratch (device globals; no allocation allowed)
__device__ float d_theta[BB*CI*TT];   // 16 MB
__device__ float d_phi[BB*CI*NN];     // 8 MB
__device__ float d_g[BB*CI*NN];       // 8 MB
__device__ float d_S[BB*CI*CI];       // 256 KB
__device__ float d_M[BB*CC*CI];       // 512 KB
__device__ float d_wy[BB*CC*TT];      // 32 MB
__device__ float d_sum[CC];
__device__ float d_sumsq[CC];
__device__ float d_scale[CC];
__device__ float d_shift[CC];

// ---------------- tf32 mma.sync helper (raw fp32 bits; BN cancels the
// systematic truncation bias as a per-channel affine distortion) ------------
__device__ __forceinline__ void mma_tf32(float* d, const uint32_t* a, const uint32_t* b) {
    asm("mma.sync.aligned.m16n8k8.row.col.f32.tf32.tf32.f32 "
        "{%0,%1,%2,%3}, {%4,%5,%6,%7}, {%8,%9}, {%0,%1,%2,%3};"
        : "+f"(d[0]), "+f"(d[1]), "+f"(d[2]), "+f"(d[3])
        : "r"(a[0]), "r"(a[1]), "r"(a[2]), "r"(a[3]), "r"(b[0]), "r"(b[1]));
}

// ---------------- cp.async helpers ------------------------------------------
__device__ __forceinline__ uint32_t smem_u32(const void* p) {
    uint32_t a;
    asm("{ .reg .u64 t; cvta.to.shared.u64 t, %1; cvt.u32.u64 %0, t; }" : "=r"(a) : "l"(p));
    return a;
}
__device__ __forceinline__ void cp16(uint32_t dst, const void* src) {
    asm volatile("cp.async.cg.shared.global [%0], [%1], 16;" :: "r"(dst), "l"(src));
}
#define CP_COMMIT() asm volatile("cp.async.commit_group;" ::: "memory")
#define CP_WAIT1()  asm volatile("cp.async.wait_group 1;" ::: "memory")
#define CP_WAIT0()  asm volatile("cp.async.wait_group 0;" ::: "memory")

// SMEM geometry: A chunk 128 rows x 32 k (row-major, pad 4); B chunk
// 32 k x 128 cols (pad 8). THREE stages, single sync per chunk:
//   wait -> __syncthreads -> stage(kc+2) -> compute(kc)
// (stage target (kc+2)%3 last held kc-1, finished before this sync).
//   A frag loads: bank = (4*lr + lq + 8ks) % 32  -> conflict-free
//   B frag loads: bank = (8*lq + lr) % 32        -> conflict-free
//   gram B (row-major like A): bank = (4*lr + lq) -> conflict-free
#define RPA 36
#define RPB 136
#define ASZ (128*RPA)           // 4608 u32
#define BSZ (32*RPB)            // 4352 u32
#define STG_C (ASZ + BSZ)       // 8960 u32
#define SMEM_C3 (3*STG_C*4)     // 107520 B
#define STG_S (ASZ + ASZ)       // 9216 u32
#define SMEM_S3 (3*STG_S*4)     // 110592 B

// Stage 128 rows x 32 floats (A-style / gram-B-style), cp.async.
__device__ __forceinline__ void stage128x32(uint32_t dstb, const float* __restrict__ src,
                                            int lds, int koff, int tid) {
#pragma unroll
    for (int i = 0; i < 4; i++) {
        int fid = i * 256 + tid;        // 0..1023
        int r = fid >> 3, q = fid & 7;
        cp16(dstb + (uint32_t)(r * RPA + q * 4) * 4,
             src + (size_t)r * lds + koff + q * 4);
    }
}
// Stage 32 k-rows x 128 floats (B-style), cp.async.
__device__ __forceinline__ void stage32x128(uint32_t dstb, const float* __restrict__ src,
                                            int lds, int koff, int t0, int tid) {
#pragma unroll
    for (int i = 0; i < 4; i++) {
        int fid = i * 256 + tid;        // 0..1023
        int k = fid >> 5, t4 = (fid & 31) << 2;
        cp16(dstb + (uint32_t)(k * RPB + t4) * 4,
             src + (size_t)(koff + k) * lds + t0 + t4);
    }
}

// Load the 4 A-fragment regs for (warp-row block ro, ks) from A-style smem.
__device__ __forceinline__ void ldA(uint32_t* a, const uint32_t* As, int ro,
                                    int k0, int lq, int lr) {
    a[0] = As[(ro + lr) * RPA + k0 + lq];
    a[1] = As[(ro + lr + 8) * RPA + k0 + lq];
    a[2] = As[(ro + lr) * RPA + k0 + 4 + lq];
    a[3] = As[(ro + lr + 8) * RPA + k0 + 4 + lq];
}

// ---------------------------------------------------------------------------
// K0: zero accumulators (S, M, sum, sumsq).
// ---------------------------------------------------------------------------
__global__ void k_init() {
    int i = blockIdx.x * blockDim.x + threadIdx.x;   // 0..65535
    if (i < BB*CI*CI) d_S[i] = 0.0f;
    d_M[2*i]   = 0.0f;
    d_M[2*i+1] = 0.0f;
    if (i < CC) { d_sum[i] = 0.0f; d_sumsq[i] = 0.0f; }
}

// ---------------------------------------------------------------------------
// K1: fused 1x1 convs via tf32 mma.sync + 3-stage cp.async, single sync.
// Block: 128 o x 128 t, K=256 in 8 chunks of 32. w = blockIdx.y + woff.
// ---------------------------------------------------------------------------
__global__ void __launch_bounds__(256, 2) k_conv_hmma(
    const float* __restrict__ x,
    const float* __restrict__ Wt, const float* __restrict__ bt,
    const float* __restrict__ Wp, const float* __restrict__ bp,
    const float* __restrict__ Wg, const float* __restrict__ bg,
    int woff)
{
    extern __shared__ uint32_t smem[];
    const uint32_t smb = smem_u32(smem);

    const int tid = threadIdx.x;
    const int warp = tid >> 5, lane = tid & 31;
    const int wo = warp >> 1, wt = warp & 1;
    const int b  = blockIdx.z;
    const int w  = blockIdx.y + woff;
    const int t0 = blockIdx.x * 128;

    const float* W    = (w == 0) ? Wt : ((w == 1) ? Wp : Wg);
    const float* bias = (w == 0) ? bt : ((w == 1) ? bp : bg);
    const float* xb   = x + (size_t)b * CC * TT;

    float acc[2][8][4];
#pragma unroll
    for (int mi = 0; mi < 2; mi++)
#pragma unroll
        for (int nt = 0; nt < 8; nt++)
#pragma unroll
            for (int j = 0; j < 4; j++) acc[mi][nt][j] = 0.0f;

    const int lq = lane & 3, lr = lane >> 2;
    const int NC = 8;

    stage128x32(smb, W, CC, 0, tid);
    stage32x128(smb + ASZ * 4, xb, TT, 0, t0, tid);
    CP_COMMIT();
    stage128x32(smb + (uint32_t)STG_C * 4, W, CC, 32, tid);
    stage32x128(smb + (uint32_t)(STG_C + ASZ) * 4, xb, TT, 32, t0, tid);
    CP_COMMIT();

    for (int kc = 0; kc < NC; kc++) {
        if (kc + 1 < NC) { CP_WAIT1(); } else { CP_WAIT0(); }
        __syncthreads();
        if (kc + 2 < NC) {
            uint32_t ab = smb + (uint32_t)(((kc + 2) % 3) * STG_C) * 4;
            stage128x32(ab, W, CC, (kc + 2) * 32, tid);
            stage32x128(ab + ASZ * 4, xb, TT, (kc + 2) * 32, t0, tid);
            CP_COMMIT();
        }
        const uint32_t* As = smem + (kc % 3) * STG_C;
        const uint32_t* Bs = As + ASZ;
#pragma unroll
        for (int ks = 0; ks < 4; ks++) {
            int k0 = ks * 8;
            uint32_t a[2][4], bf[8][2];
#pragma unroll
            for (int mi = 0; mi < 2; mi++)
                ldA(a[mi], As, (wo * 2 + mi) * 16, k0, lq, lr);
            int tb = wt * 64 + lr;
#pragma unroll
            for (int nt = 0; nt < 8; nt++) {
                bf[nt][0] = Bs[(k0 + lq) * RPB + tb + nt * 8];
                bf[nt][1] = Bs[(k0 + 4 + lq) * RPB + tb + nt * 8];
            }
#pragma unroll
            for (int mi = 0; mi < 2; mi++)
#pragma unroll
                for (int nt = 0; nt < 8; nt++)
                    mma_tf32(acc[mi][nt], a[mi], bf[nt]);
        }
    }

    // Epilogue. D frag: d0=D[lr][2lq], d1=D[lr][2lq+1], d2=D[lr+8][2lq], d3=D[lr+8][2lq+1]
    if (w == 0) {
        float* dst = d_theta + (size_t)b * CI * TT;
#pragma unroll
        for (int mi = 0; mi < 2; mi++) {
            int o1 = wo * 32 + mi * 16 + lr;
            int o2 = o1 + 8;
            float bz1 = bias[o1], bz2 = bias[o2];
#pragma unroll
            for (int nt = 0; nt < 8; nt++) {
                int t = t0 + wt * 64 + nt * 8 + 2 * lq;
                *(float2*)(dst + (size_t)o1 * TT + t) =
                    make_float2(acc[mi][nt][0] + bz1, acc[mi][nt][1] + bz1);
                *(float2*)(dst + (size_t)o2 * TT + t) =
                    make_float2(acc[mi][nt][2] + bz2, acc[mi][nt][3] + bz2);
            }
        }
    } else {
        float* dst = ((w == 1) ? d_phi : d_g) + (size_t)b * CI * NN;
#pragma unroll
        for (int mi = 0; mi < 2; mi++) {
            int o1 = wo * 32 + mi * 16 + lr;
            int o2 = o1 + 8;
            float bz1 = bias[o1], bz2 = bias[o2];
#pragma unroll
            for (int nt = 0; nt < 8; nt++) {
                int n = (t0 >> 1) + wt * 32 + nt * 4 + lq;
                dst[(size_t)o1 * NN + n] = fmaxf(acc[mi][nt][0], acc[mi][nt][1]) + bz1;
                dst[(size_t)o2 * NN + n] = fmaxf(acc[mi][nt][2], acc[mi][nt][3]) + bz2;
            }
        }
    }
}

// ---------------------------------------------------------------------------
// K2: S[b,a,ci] = sum_n phi[b,a,n]*g[b,ci,n], tf32 mma + 3-stage pipeline.
// Split-K: 16 slabs of 256 n (8 chunks of 32). Atomic reduce into d_S.
// ---------------------------------------------------------------------------
__global__ void __launch_bounds__(256, 2) k_S_hmma()
{
    extern __shared__ uint32_t smem[];
    const uint32_t smb = smem_u32(smem);

    const int tid = threadIdx.x;
    const int warp = tid >> 5, lane = tid & 31;
    const int wo = warp >> 1, wt = warp & 1;
    const int b  = blockIdx.y;
    const int n0 = blockIdx.x * 256;

    const float* P = d_phi + (size_t)b * CI * NN;
    const float* G = d_g   + (size_t)b * CI * NN;

    float acc[2][8][4];
#pragma unroll
    for (int mi = 0; mi < 2; mi++)
#pragma unroll
        for (int nt = 0; nt < 8; nt++)
#pragma unroll
            for (int j = 0; j < 4; j++) acc[mi][nt][j] = 0.0f;

    const int lq = lane & 3, lr = lane >> 2;
    const int NC = 8;

    stage128x32(smb, P, NN, n0, tid);
    stage128x32(smb + ASZ * 4, G, NN, n0, tid);
    CP_COMMIT();
    stage128x32(smb + (uint32_t)STG_S * 4, P, NN, n0 + 32, tid);
    stage128x32(smb + (uint32_t)(STG_S + ASZ) * 4, G, NN, n0 + 32, tid);
    CP_COMMIT();

    for (int kc = 0; kc < NC; kc++) {
        if (kc + 1 < NC) { CP_WAIT1(); } else { CP_WAIT0(); }
        __syncthreads();
        if (kc + 2 < NC) {
            uint32_t ab = smb + (uint32_t)(((kc + 2) % 3) * STG_S) * 4;
            stage128x32(ab, P, NN, n0 + (kc + 2) * 32, tid);
            stage128x32(ab + ASZ * 4, G, NN, n0 + (kc + 2) * 32, tid);
            CP_COMMIT();
        }
        const uint32_t* As  = smem + (kc % 3) * STG_S;
        const uint32_t* Bs2 = As + ASZ;
#pragma unroll
        for (int ks = 0; ks < 4; ks++) {
            int k0 = ks * 8;
            uint32_t a[2][4], bf[8][2];
#pragma unroll
            for (int mi = 0; mi < 2; mi++)
                ldA(a[mi], As, (wo * 2 + mi) * 16, k0, lq, lr);
#pragma unroll
            for (int nt = 0; nt < 8; nt++) {
                int n = wt * 64 + nt * 8 + lr;
                bf[nt][0] = Bs2[n * RPA + k0 + lq];
                bf[nt][1] = Bs2[n * RPA + k0 + 4 + lq];
            }
#pragma unroll
            for (int mi = 0; mi < 2; mi++)
#pragma unroll
                for (int nt = 0; nt < 8; nt++)
                    mma_tf32(acc[mi][nt], a[mi], bf[nt]);
        }
    }

    float* Sp = d_S + (size_t)b * CI * CI;
#pragma unroll
    for (int mi = 0; mi < 2; mi++) {
        int a1 = wo * 32 + mi * 16 + lr;
        int a2 = a1 + 8;
#pragma unroll
        for (int nt = 0; nt < 8; nt++) {
            int ci = wt * 64 + nt * 8 + 2 * lq;
            atomicAdd(&Sp[(size_t)a1 * CI + ci],     acc[mi][nt][0]);
            atomicAdd(&Sp[(size_t)a1 * CI + ci + 1], acc[mi][nt][1]);
            atomicAdd(&Sp[(size_t)a2 * CI + ci],     acc[mi][nt][2]);
            atomicAdd(&Sp[(size_t)a2 * CI + ci + 1], acc[mi][nt][3]);
        }
    }
}

// ---------------------------------------------------------------------------
// K3: M[b,o,a] = (1/N) * sum_k w_w[o,k] * S[b,a,k]. Split-k(2) SMEM GEMM.
// ---------------------------------------------------------------------------
__global__ __launch_bounds__(256) void k_M2(const float* __restrict__ ww)
{
    __shared__ float ws[32][65];
    __shared__ float ss[32][65];

    const int tid = threadIdx.x;
    const int b  = blockIdx.x >> 6;
    const int ob = (blockIdx.x >> 3) & 7;
    const int ab = (blockIdx.x >> 1) & 3;
    const int kh = (blockIdx.x & 1) * 64;

#pragma unroll
    for (int i = 0; i < 2; i++) {
        int fid = i * 256 + tid;
        int r = fid >> 4, c4 = fid & 15;
        float4 v = *(const float4*)(ww + (size_t)(ob * 32 + r) * CI + kh + 4 * c4);
        ws[r][4*c4+0] = v.x; ws[r][4*c4+1] = v.y; ws[r][4*c4+2] = v.z; ws[r][4*c4+3] = v.w;
        float4 u = *(const float4*)(d_S + (size_t)b * CI * CI + (size_t)(ab * 32 + r) * CI + kh + 4 * c4);
        ss[r][4*c4+0] = u.x; ss[r][4*c4+1] = u.y; ss[r][4*c4+2] = u.z; ss[r][4*c4+3] = u.w;
    }
    __syncthreads();

    const int ty = tid >> 3;
    const int tx = tid & 7;
    float acc[4] = {0.f, 0.f, 0.f, 0.f};
#pragma unroll
    for (int k = 0; k < 64; k++) {
        float wv = ws[ty][k];
#pragma unroll
        for (int j = 0; j < 4; j++) acc[j] = fmaf(wv, ss[4*tx+j][k], acc[j]);
    }
    const float invN = 1.0f / NN;
    float* Mp = d_M + (size_t)b * CC * CI + (size_t)(ob * 32 + ty) * CI + ab * 32 + 4 * tx;
#pragma unroll
    for (int j = 0; j < 4; j++) atomicAdd(&Mp[j], acc[j] * invN);
}

// ---------------------------------------------------------------------------
// K4: wy = M @ theta + w_b via tf32 mma + 3-stage pipeline; fused BN sums.
// Block: 128 o x 128 t, K=128 in 4 chunks of 32.
// ---------------------------------------------------------------------------
__global__ void __launch_bounds__(256, 2) k_wy_hmma(const float* __restrict__ wb)
{
    extern __shared__ uint32_t smem[];
    const uint32_t smb = smem_u32(smem);

    const int tid = threadIdx.x;
    const int warp = tid >> 5, lane = tid & 31;
    const int wo = warp >> 1, wt = warp & 1;
    const int b  = blockIdx.z;
    const int o0 = blockIdx.y * 128;
    const int t0 = blockIdx.x * 128;

    const float* Mp = d_M + (size_t)b * CC * CI + (size_t)o0 * CI;
    const float* Th = d_theta + (size_t)b * CI * TT;

    float acc[2][8][4];
#pragma unroll
    for (int mi = 0; mi < 2; mi++)
#pragma unroll
        for (int nt = 0; nt < 8; nt++)
#pragma unroll
            for (int j = 0; j < 4; j++) acc[mi][nt][j] = 0.0f;

    const int lq = lane & 3, lr = lane >> 2;
    const int NC = 4;

    stage128x32(smb, Mp, CI, 0, tid);
    stage32x128(smb + ASZ * 4, Th, TT, 0, t0, tid);
    CP_COMMIT();
    stage128x32(smb + (uint32_t)STG_C * 4, Mp, CI, 32, tid);
    stage32x128(smb + (uint32_t)(STG_C + ASZ) * 4, Th, TT, 32, t0, tid);
    CP_COMMIT();

    for (int kc = 0; kc < NC; kc++) {
        if (kc + 1 < NC) { CP_WAIT1(); } else { CP_WAIT0(); }
        __syncthreads();
        if (kc + 2 < NC) {
            uint32_t ab = smb + (uint32_t)(((kc + 2) % 3) * STG_C) * 4;
            stage128x32(ab, Mp, CI, (kc + 2) * 32, tid);
            stage32x128(ab + ASZ * 4, Th, TT, (kc + 2) * 32, t0, tid);
            CP_COMMIT();
        }
        const uint32_t* As = smem + (kc % 3) * STG_C;
        const uint32_t* Bs = As + ASZ;
#pragma unroll
        for (int ks = 0; ks < 4; ks++) {
            int k0 = ks * 8;
            uint32_t a[2][4], bf[8][2];
#pragma unroll
            for (int mi = 0; mi < 2; mi++)
                ldA(a[mi], As, (wo * 2 + mi) * 16, k0, lq, lr);
            int tb = wt * 64 + lr;
#pragma unroll
            for (int nt = 0; nt < 8; nt++) {
                bf[nt][0] = Bs[(k0 + lq) * RPB + tb + nt * 8];
                bf[nt][1] = Bs[(k0 + 4 + lq) * RPB + tb + nt * 8];
            }
#pragma unroll
            for (int mi = 0; mi < 2; mi++)
#pragma unroll
                for (int nt = 0; nt < 8; nt++)
                    mma_tf32(acc[mi][nt], a[mi], bf[nt]);
        }
    }

    float* wyp = d_wy + (size_t)b * CC * TT;
#pragma unroll
    for (int mi = 0; mi < 2; mi++) {
        int o1 = o0 + wo * 32 + mi * 16 + lr;
        int o2 = o1 + 8;
        float bz1 = wb[o1], bz2 = wb[o2];
        float s1 = 0.f, q1 = 0.f, s2 = 0.f, q2 = 0.f;
#pragma unroll
        for (int nt = 0; nt < 8; nt++) {
            int t = t0 + wt * 64 + nt * 8 + 2 * lq;
            float v0 = acc[mi][nt][0] + bz1, v1 = acc[mi][nt][1] + bz1;
            float v2 = acc[mi][nt][2] + bz2, v3 = acc[mi][nt][3] + bz2;
            s1 += v0 + v1; q1 = fmaf(v0, v0, q1); q1 = fmaf(v1, v1, q1);
            s2 += v2 + v3; q2 = fmaf(v2, v2, q2); q2 = fmaf(v3, v3, q2);
            *(float2*)(wyp + (size_t)o1 * TT + t) = make_float2(v0, v1);
            *(float2*)(wyp + (size_t)o2 * TT + t) = make_float2(v2, v3);
        }
#pragma unroll
        for (int off = 1; off < 4; off <<= 1) {
            s1 += __shfl_xor_sync(0xffffffffu, s1, off);
            q1 += __shfl_xor_sync(0xffffffffu, q1, off);
            s2 += __shfl_xor_sync(0xffffffffu, s2, off);
            q2 += __shfl_xor_sync(0xffffffffu, q2, off);
        }
        if (lq == 0) {
            atomicAdd(&d_sum[o1], s1);
            atomicAdd(&d_sumsq[o1], q1);
            atomicAdd(&d_sum[o2], s2);
            atomicAdd(&d_sumsq[o2], q2);
        }
    }
}

// ---------------------------------------------------------------------------
// K5: finalize BN statistics.
// ---------------------------------------------------------------------------
__global__ void k_stats(const float* __restrict__ gamma, const float* __restrict__ beta)
{
    int o = threadIdx.x;
    if (o < CC) {
        float mean = d_sum[o]   * (1.0f / BNT);
        float var  = d_sumsq[o] * (1.0f / BNT) - mean * mean;
        float sc   = gamma[o] * rsqrtf(var + 1e-5f);
        d_scale[o] = sc;
        d_shift[o] = beta[o] - mean * sc;
    }
}

// ---------------------------------------------------------------------------
// K6: out = scale[o]*wy + shift[o] + x
// ---------------------------------------------------------------------------
__global__ __launch_bounds__(256) void k_out(const float* __restrict__ x,
                                             float* __restrict__ out)
{
    size_t i4 = (size_t)blockIdx.x * 256 + threadIdx.x;
    int o = (int)((i4 >> 11) & 255);
    float sc = d_scale[o], sh = d_shift[o];
    float4 w  = *((const float4*)d_wy + i4);
    float4 xv = *((const float4*)x + i4);
    float4 r;
    r.x = fmaf(sc, w.x, sh) + xv.x;
    r.y = fmaf(sc, w.y, sh) + xv.y;
    r.z = fmaf(sc, w.z, sh) + xv.z;
    r.w = fmaf(sc, w.w, sh) + xv.w;
    ((float4*)out)[i4] = r;
}

// ---------------------------------------------------------------------------
// Launch: three-stream fork/join (graph-capturable).
//   s2            : init (off the critical path)
//   s1 (high prio): conv(phi,g) -> [wait init] -> S -> M
//   s0 (default)  : conv(theta)  [backfills SMs while S/M run]
//   join          : wy -> stats -> out
// ---------------------------------------------------------------------------
extern "C" void kernel_launch(void* const* d_in, const int* in_sizes, int n_in,
                              void* d_out, int out_size)
{
    const float* x     = (const float*)d_in[0];
    const float* tw    = (const float*)d_in[1];
    const float* tb    = (const float*)d_in[2];
    const float* pw    = (const float*)d_in[3];
    const float* pb    = (const float*)d_in[4];
    const float* gw    = (const float*)d_in[5];
    const float* gb    = (const float*)d_in[6];
    const float* ww    = (const float*)d_in[7];
    const float* wb    = (const float*)d_in[8];
    const float* gamma = (const float*)d_in[9];
    const float* beta  = (const float*)d_in[10];
    float* out = (float*)d_out;

    static cudaStream_t s1 = nullptr, s2 = nullptr;
    static cudaEvent_t eF = nullptr, eI = nullptr, eJ = nullptr;
    static int init_done = 0;
    if (!init_done) {
        cudaFuncSetAttribute(k_conv_hmma, cudaFuncAttributeMaxDynamicSharedMemorySize, SMEM_C3);
        cudaFuncSetAttribute(k_S_hmma,    cudaFuncAttributeMaxDynamicSharedMemorySize, SMEM_S3);
        cudaFuncSetAttribute(k_wy_hmma,   cudaFuncAttributeMaxDynamicSharedMemorySize, SMEM_C3);
        int lo, hi;
        cudaDeviceGetStreamPriorityRange(&lo, &hi);
        cudaStreamCreateWithPriority(&s1, cudaStreamNonBlocking, hi);
        cudaStreamCreateWithPriority(&s2, cudaStreamNonBlocking, hi);
        cudaEventCreateWithFlags(&eF, cudaEventDisableTiming);
        cudaEventCreateWithFlags(&eI, cudaEventDisableTiming);
        cudaEventCreateWithFlags(&eJ, cudaEventDisableTiming);
        init_done = 1;
    }

    // Fork: s1 and s2 branch off the main (captured) stream.
    cudaEventRecord(eF, 0);
    cudaStreamWaitEvent(s1, eF, 0);
    cudaStreamWaitEvent(s2, eF, 0);

    // s2: zero-init accumulators, off the critical path.
    k_init<<<256, 256, 0, s2>>>();
    cudaEventRecord(eI, s2);

    // s1: phi+g convs immediately; S and M after init lands.
    k_conv_hmma<<<dim3(TT / 128, 2, BB), 256, SMEM_C3, s1>>>(x, tw, tb, pw, pb, gw, gb, 1);
    cudaStreamWaitEvent(s1, eI, 0);
    k_S_hmma<<<dim3(16, BB), 256, SMEM_S3, s1>>>();
    k_M2<<<256, 256, 0, s1>>>(ww);
    cudaEventRecord(eJ, s1);

    // main stream: theta conv runs concurrently (backfills idle SMs).
    k_conv_hmma<<<dim3(TT / 128, 1, BB), 256, SMEM_C3>>>(x, tw, tb, pw, pb, gw, gb, 0);

    // Join, then the dependent tail (eJ implies eI, so wy's atomics are safe).
    cudaStreamWaitEvent(0, eJ, 0);
    k_wy_hmma<<<dim3(TT / 128, 2, BB), 256, SMEM_C3>>>(wb);
    k_stats<<<1, 256>>>(gamma, beta);
    k_out<<<8192, 256>>>(x, out);
}

// round 14
// speedup vs baseline: 1.2094x; 1.2094x over previous
#include <cuda_runtime.h>
#include <cuda_fp16.h>
#include <cstdint>

#define BB 4
#define CC 256
#define CI 128
#define TT 8192
#define NN 4096
#define BNT (BB*TT)

// Scratch (device globals; no allocation allowed). 16B-aligned for cp.async.
__device__ __align__(16) __half d_xt16[BB*TT*CC];  // x^T [b][t][c], 16 MB
__device__ __align__(16) __half d_w16[3*CI*CC];    // theta/phi/g weights fp16
__device__ __align__(16) __half d_th16[BB*TT*CI];  // theta^T [b][t][a], 8 MB
__device__ __align__(16) __half d_p16[BB*CI*NN];   // phi [b][ci][n], 4 MB
__device__ __align__(16) __half d_g16[BB*CI*NN];   // g   [b][ci][n], 4 MB
__device__ __align__(16) __half d_M16[BB*CC*CI];   // M [b][o][a] fp16
__device__ float d_S[BB*CI*CI];
__device__ float d_wy[BB*CC*TT];
__device__ float d_sum[CC];
__device__ float d_sumsq[CC];
__device__ float d_scale[CC];
__device__ float d_shift[CC];

// ---------------- fp16 mma.sync (m16n8k16), fp32 accumulate -----------------
__device__ __forceinline__ void mma_f16(float* d, const uint32_t* a, const uint32_t* b) {
    asm("mma.sync.aligned.m16n8k16.row.col.f32.f16.f16.f32 "
        "{%0,%1,%2,%3}, {%4,%5,%6,%7}, {%8,%9}, {%0,%1,%2,%3};"
        : "+f"(d[0]), "+f"(d[1]), "+f"(d[2]), "+f"(d[3])
        : "r"(a[0]), "r"(a[1]), "r"(a[2]), "r"(a[3]), "r"(b[0]), "r"(b[1]));
}

// ---------------- cp.async helpers ------------------------------------------
__device__ __forceinline__ uint32_t smem_u32(const void* p) {
    uint32_t a;
    asm("{ .reg .u64 t; cvta.to.shared.u64 t, %1; cvt.u32.u64 %0, t; }" : "=r"(a) : "l"(p));
    return a;
}
__device__ __forceinline__ void cp16(uint32_t dst, const void* src) {
    asm volatile("cp.async.cg.shared.global [%0], [%1], 16;" :: "r"(dst), "l"(src));
}
#define CP_COMMIT() asm volatile("cp.async.commit_group;" ::: "memory")
#define CP_WAIT1()  asm volatile("cp.async.wait_group 1;" ::: "memory")
#define CP_WAIT0()  asm volatile("cp.async.wait_group 0;" ::: "memory")

// SMEM: per stage two fp16 tiles, each 128 rows x 64 k halves = 32 u32/row,
// padded to 36 u32 (pitch % 32 == 4 -> frag-load bank = 4*lr + lq + 8*ks,
// conflict-free). Double-buffered.
#define PIT 36
#define TSZ (128*PIT)          // 4608 u32 per tile
#define STGH (2*TSZ)           // 9216 u32 per stage
#define SMEM16 (2*STGH*4)      // 73728 B

// Stage 128 rows x 64 halves from row-major fp16 src (ld = lds halves).
__device__ __forceinline__ void stage_h(uint32_t dstb, const __half* __restrict__ src,
                                        int lds, int koff, int tid) {
#pragma unroll
    for (int i = 0; i < 4; i++) {
        int fid = i * 256 + tid;        // 0..1023 16B-chunks
        int r = fid >> 3, q = fid & 7;
        cp16(dstb + (uint32_t)(r * PIT + q * 4) * 4,
             src + (size_t)r * lds + koff + q * 8);
    }
}

// A-fragment (4 u32) for m16n8k16 from row-major-k tile. ro = warp row base.
__device__ __forceinline__ void ldA16(uint32_t* a, const uint32_t* As, int ro,
                                      int k0, int lq, int lr) {
    a[0] = As[(ro + lr) * PIT + k0 + lq];
    a[1] = As[(ro + lr + 8) * PIT + k0 + lq];
    a[2] = As[(ro + lr) * PIT + k0 + 4 + lq];
    a[3] = As[(ro + lr + 8) * PIT + k0 + 4 + lq];
}

// ---------------------------------------------------------------------------
// K0: zero accumulators.
// ---------------------------------------------------------------------------
__global__ void k_init() {
    int i = blockIdx.x * blockDim.x + threadIdx.x;   // 0..65535
    d_S[i] = 0.0f;
    if (i < CC) { d_sum[i] = 0.0f; d_sumsq[i] = 0.0f; }
}

// Convert the three 128x256 weight matrices to fp16 (packed [3][128][256]).
__global__ void k_wcvt(const float* __restrict__ tw, const float* __restrict__ pw,
                       const float* __restrict__ gw) {
    int i = blockIdx.x * 256 + threadIdx.x;          // 0..98303 (grid 384)
    const float* src = (i < CI*CC) ? tw : ((i < 2*CI*CC) ? pw : gw);
    d_w16[i] = __float2half(src[i & (CI*CC - 1)]);
}

// Transpose+convert x [b][c][t] fp32 -> d_xt16 [b][t][c] fp16. 64x64 tiles.
__global__ __launch_bounds__(256) void k_xt(const float* __restrict__ x) {
    __shared__ float sm[64][65];
    const int b = blockIdx.z, c0 = blockIdx.y * 64, t0 = blockIdx.x * 64;
    const float* xb = x + ((size_t)b * CC + c0) * TT + t0;
    const int tid = threadIdx.x;
#pragma unroll
    for (int i = 0; i < 4; i++) {
        int id = i * 256 + tid;          // 0..1023 float4s
        int c = id >> 4, t4 = (id & 15) * 4;
        float4 v = *(const float4*)(xb + (size_t)c * TT + t4);
        sm[c][t4] = v.x; sm[c][t4+1] = v.y; sm[c][t4+2] = v.z; sm[c][t4+3] = v.w;
    }
    __syncthreads();
    __half* dst = d_xt16 + ((size_t)b * TT + t0) * CC + c0;
#pragma unroll
    for (int i = 0; i < 8; i++) {
        int id = i * 256 + tid;          // 0..2047 half2s
        int t = id >> 5, cp = id & 31;
        *(__half2*)(dst + (size_t)t * CC + 2 * cp) =
            __floats2half2_rn(sm[2*cp][t], sm[2*cp+1][t]);
    }
}

// ---------------------------------------------------------------------------
// K1a: theta conv. A = x^T tile (M=t), B = W_theta (N=o). K=256 in 4 chunks
// of 64. Output theta^T fp16 [t][a] (half2 stores).
// ---------------------------------------------------------------------------
__global__ void __launch_bounds__(256, 2) k_conv_th(const float* __restrict__ bt)
{
    extern __shared__ uint32_t smem[];
    const uint32_t smb = smem_u32(smem);

    const int tid = threadIdx.x;
    const int warp = tid >> 5, lane = tid & 31;
    const int wo = warp >> 1, wt = warp & 1;
    const int b  = blockIdx.z;
    const int t0 = blockIdx.x * 128;
    const __half* Asrc = d_xt16 + ((size_t)b * TT + t0) * CC;
    const __half* Bsrc = d_w16;   // theta weights

    float acc[2][8][4];
#pragma unroll
    for (int mi = 0; mi < 2; mi++)
#pragma unroll
        for (int nt = 0; nt < 8; nt++)
#pragma unroll
            for (int j = 0; j < 4; j++) acc[mi][nt][j] = 0.0f;

    const int lq = lane & 3, lr = lane >> 2;
    const int NC = 4;

    stage_h(smb, Asrc, CC, 0, tid);
    stage_h(smb + TSZ * 4, Bsrc, CC, 0, tid);
    CP_COMMIT();

    for (int kc = 0; kc < NC; kc++) {
        if (kc + 1 < NC) {
            uint32_t ab = smb + (uint32_t)(((kc + 1) & 1) * STGH) * 4;
            stage_h(ab, Asrc, CC, (kc + 1) * 64, tid);
            stage_h(ab + TSZ * 4, Bsrc, CC, (kc + 1) * 64, tid);
            CP_COMMIT();
            CP_WAIT1();
        } else {
            CP_WAIT0();
        }
        __syncthreads();
        const uint32_t* As = smem + (kc & 1) * STGH;
        const uint32_t* Bs = As + TSZ;
#pragma unroll
        for (int ks = 0; ks < 4; ks++) {
            int k0 = ks * 8;
            uint32_t a[2][4], bf[8][2];
#pragma unroll
            for (int mi = 0; mi < 2; mi++)
                ldA16(a[mi], As, (wo * 2 + mi) * 16, k0, lq, lr);
#pragma unroll
            for (int nt = 0; nt < 8; nt++) {
                int n = wt * 64 + nt * 8 + lr;
                bf[nt][0] = Bs[n * PIT + k0 + lq];
                bf[nt][1] = Bs[n * PIT + k0 + 4 + lq];
            }
#pragma unroll
            for (int mi = 0; mi < 2; mi++)
#pragma unroll
                for (int nt = 0; nt < 8; nt++)
                    mma_f16(acc[mi][nt], a[mi], bf[nt]);
        }
        __syncthreads();
    }

    // D[m=t][n=o]; d0,d1 = cols o,o+1 at row t (half2-friendly).
    __half* dst = d_th16 + ((size_t)b * TT + t0) * CI;
#pragma unroll
    for (int mi = 0; mi < 2; mi++) {
        int t1 = wo * 32 + mi * 16 + lr;
        int t2 = t1 + 8;
#pragma unroll
        for (int nt = 0; nt < 8; nt++) {
            int o = wt * 64 + nt * 8 + 2 * lq;
            float b0 = bt[o], b1 = bt[o + 1];
            *(__half2*)(dst + (size_t)t1 * CI + o) =
                __floats2half2_rn(acc[mi][nt][0] + b0, acc[mi][nt][1] + b1);
            *(__half2*)(dst + (size_t)t2 * CI + o) =
                __floats2half2_rn(acc[mi][nt][2] + b0, acc[mi][nt][3] + b1);
        }
    }
}

// ---------------------------------------------------------------------------
// K1b: phi/g conv (blockIdx.y selects). A = W (M=o), B = x^T tile (N=t),
// so the maxpool t-pair (d0,d1) is in-thread. Output fp16 [ci][n].
// ---------------------------------------------------------------------------
__global__ void __launch_bounds__(256, 2) k_conv_pg(const float* __restrict__ pb,
                                                    const float* __restrict__ gb)
{
    extern __shared__ uint32_t smem[];
    const uint32_t smb = smem_u32(smem);

    const int tid = threadIdx.x;
    const int warp = tid >> 5, lane = tid & 31;
    const int wo = warp >> 1, wt = warp & 1;
    const int b  = blockIdx.z;
    const int w  = blockIdx.y;               // 0 = phi, 1 = g
    const int t0 = blockIdx.x * 128;
    const __half* Asrc = d_w16 + (size_t)(1 + w) * CI * CC;
    const __half* Bsrc = d_xt16 + ((size_t)b * TT + t0) * CC;
    const float* bias = (w == 0) ? pb : gb;

    float acc[2][8][4];
#pragma unroll
    for (int mi = 0; mi < 2; mi++)
#pragma unroll
        for (int nt = 0; nt < 8; nt++)
#pragma unroll
            for (int j = 0; j < 4; j++) acc[mi][nt][j] = 0.0f;

    const int lq = lane & 3, lr = lane >> 2;
    const int NC = 4;

    stage_h(smb, Asrc, CC, 0, tid);
    stage_h(smb + TSZ * 4, Bsrc, CC, 0, tid);
    CP_COMMIT();

    for (int kc = 0; kc < NC; kc++) {
        if (kc + 1 < NC) {
            uint32_t ab = smb + (uint32_t)(((kc + 1) & 1) * STGH) * 4;
            stage_h(ab, Asrc, CC, (kc + 1) * 64, tid);
            stage_h(ab + TSZ * 4, Bsrc, CC, (kc + 1) * 64, tid);
            CP_COMMIT();
            CP_WAIT1();
        } else {
            CP_WAIT0();
        }
        __syncthreads();
        const uint32_t* As = smem + (kc & 1) * STGH;
        const uint32_t* Bs = As + TSZ;
#pragma unroll
        for (int ks = 0; ks < 4; ks++) {
            int k0 = ks * 8;
            uint32_t a[2][4], bf[8][2];
#pragma unroll
            for (int mi = 0; mi < 2; mi++)
                ldA16(a[mi], As, (wo * 2 + mi) * 16, k0, lq, lr);
#pragma unroll
            for (int nt = 0; nt < 8; nt++) {
                int n = wt * 64 + nt * 8 + lr;
                bf[nt][0] = Bs[n * PIT + k0 + lq];
                bf[nt][1] = Bs[n * PIT + k0 + 4 + lq];
            }
#pragma unroll
            for (int mi = 0; mi < 2; mi++)
#pragma unroll
                for (int nt = 0; nt < 8; nt++)
                    mma_f16(acc[mi][nt], a[mi], bf[nt]);
        }
        __syncthreads();
    }

    // D[m=o][n=t]; maxpool over the in-thread t-pair (d0,d1) and (d2,d3).
    __half* dst = ((w == 0) ? d_p16 : d_g16) + (size_t)b * CI * NN + (t0 >> 1);
#pragma unroll
    for (int mi = 0; mi < 2; mi++) {
        int o1 = wo * 32 + mi * 16 + lr;
        int o2 = o1 + 8;
        float bz1 = bias[o1], bz2 = bias[o2];
#pragma unroll
        for (int nt = 0; nt < 8; nt++) {
            int np = wt * 32 + nt * 4 + lq;
            dst[(size_t)o1 * NN + np] =
                __float2half(fmaxf(acc[mi][nt][0], acc[mi][nt][1]) + bz1);
            dst[(size_t)o2 * NN + np] =
                __float2half(fmaxf(acc[mi][nt][2], acc[mi][nt][3]) + bz2);
        }
    }
}

// ---------------------------------------------------------------------------
// K2: S = phi . g^T. Split-K: 16 slabs of 256 n (4 chunks of 64). fp32 atomics.
// ---------------------------------------------------------------------------
__global__ void __launch_bounds__(256, 2) k_S16()
{
    extern __shared__ uint32_t smem[];
    const uint32_t smb = smem_u32(smem);

    const int tid = threadIdx.x;
    const int warp = tid >> 5, lane = tid & 31;
    const int wo = warp >> 1, wt = warp & 1;
    const int b  = blockIdx.y;
    const int n0 = blockIdx.x * 256;
    const __half* P = d_p16 + (size_t)b * CI * NN;
    const __half* G = d_g16 + (size_t)b * CI * NN;

    float acc[2][8][4];
#pragma unroll
    for (int mi = 0; mi < 2; mi++)
#pragma unroll
        for (int nt = 0; nt < 8; nt++)
#pragma unroll
            for (int j = 0; j < 4; j++) acc[mi][nt][j] = 0.0f;

    const int lq = lane & 3, lr = lane >> 2;
    const int NC = 4;

    stage_h(smb, P, NN, n0, tid);
    stage_h(smb + TSZ * 4, G, NN, n0, tid);
    CP_COMMIT();

    for (int kc = 0; kc < NC; kc++) {
        if (kc + 1 < NC) {
            uint32_t ab = smb + (uint32_t)(((kc + 1) & 1) * STGH) * 4;
            stage_h(ab, P, NN, n0 + (kc + 1) * 64, tid);
            stage_h(ab + TSZ * 4, G, NN, n0 + (kc + 1) * 64, tid);
            CP_COMMIT();
            CP_WAIT1();
        } else {
            CP_WAIT0();
        }
        __syncthreads();
        const uint32_t* As = smem + (kc & 1) * STGH;
        const uint32_t* Bs = As + TSZ;
#pragma unroll
        for (int ks = 0; ks < 4; ks++) {
            int k0 = ks * 8;
            uint32_t a[2][4], bf[8][2];
#pragma unroll
            for (int mi = 0; mi < 2; mi++)
                ldA16(a[mi], As, (wo * 2 + mi) * 16, k0, lq, lr);
#pragma unroll
            for (int nt = 0; nt < 8; nt++) {
                int n = wt * 64 + nt * 8 + lr;
                bf[nt][0] = Bs[n * PIT + k0 + lq];
                bf[nt][1] = Bs[n * PIT + k0 + 4 + lq];
            }
#pragma unroll
            for (int mi = 0; mi < 2; mi++)
#pragma unroll
                for (int nt = 0; nt < 8; nt++)
                    mma_f16(acc[mi][nt], a[mi], bf[nt]);
        }
        __syncthreads();
    }

    float* Sp = d_S + (size_t)b * CI * CI;
#pragma unroll
    for (int mi = 0; mi < 2; mi++) {
        int a1 = wo * 32 + mi * 16 + lr;
        int a2 = a1 + 8;
#pragma unroll
        for (int nt = 0; nt < 8; nt++) {
            int ci = wt * 64 + nt * 8 + 2 * lq;
            atomicAdd(&Sp[(size_t)a1 * CI + ci],     acc[mi][nt][0]);
            atomicAdd(&Sp[(size_t)a1 * CI + ci + 1], acc[mi][nt][1]);
            atomicAdd(&Sp[(size_t)a2 * CI + ci],     acc[mi][nt][2]);
            atomicAdd(&Sp[(size_t)a2 * CI + ci + 1], acc[mi][nt][3]);
        }
    }
}

// ---------------------------------------------------------------------------
// K3: M[b,o,a] = (1/N) sum_k ww[o,k] S[b,a,k]; fp32 SIMT, writes fp16 M.
// Grid: 128 = b(4) x o-tile(8, 32 rows) x a-tile(4, 32 rows). Direct store.
// ---------------------------------------------------------------------------
__global__ __launch_bounds__(256) void k_M2f(const float* __restrict__ ww)
{
    __shared__ float ws[32][129];
    __shared__ float ss[32][129];

    const int tid = threadIdx.x;
    const int b  = blockIdx.x >> 5;
    const int ob = (blockIdx.x >> 2) & 7;
    const int ab = blockIdx.x & 3;

#pragma unroll
    for (int i = 0; i < 4; i++) {
        int fid = i * 256 + tid;
        int r = fid >> 5, c4 = fid & 31;
        float4 v = *(const float4*)(ww + (size_t)(ob * 32 + r) * CI + 4 * c4);
        ws[r][4*c4+0] = v.x; ws[r][4*c4+1] = v.y; ws[r][4*c4+2] = v.z; ws[r][4*c4+3] = v.w;
        float4 u = *(const float4*)(d_S + (size_t)b * CI * CI + (size_t)(ab * 32 + r) * CI + 4 * c4);
        ss[r][4*c4+0] = u.x; ss[r][4*c4+1] = u.y; ss[r][4*c4+2] = u.z; ss[r][4*c4+3] = u.w;
    }
    __syncthreads();

    const int ty = tid >> 3;
    const int tx = tid & 7;
    float acc[4] = {0.f, 0.f, 0.f, 0.f};
#pragma unroll
    for (int k = 0; k < CI; k++) {
        float wv = ws[ty][k];
#pragma unroll
        for (int j = 0; j < 4; j++) acc[j] = fmaf(wv, ss[4*tx+j][k], acc[j]);
    }
    const float invN = 1.0f / NN;
    __half* Mp = d_M16 + (size_t)b * CC * CI + (size_t)(ob * 32 + ty) * CI + ab * 32 + 4 * tx;
#pragma unroll
    for (int j = 0; j < 4; j++) Mp[j] = __float2half(acc[j] * invN);
}

// ---------------------------------------------------------------------------
// K4: wy = M16 . theta^T + w_b (fp16 mma); fused BN sums. K=128, 2 chunks.
// ---------------------------------------------------------------------------
__global__ void __launch_bounds__(256, 2) k_wy16(const float* __restrict__ wb)
{
    extern __shared__ uint32_t smem[];
    const uint32_t smb = smem_u32(smem);

    const int tid = threadIdx.x;
    const int warp = tid >> 5, lane = tid & 31;
    const int wo = warp >> 1, wt = warp & 1;
    const int b  = blockIdx.z;
    const int o0 = blockIdx.y * 128;
    const int t0 = blockIdx.x * 128;
    const __half* Mp = d_M16 + ((size_t)b * CC + o0) * CI;
    const __half* Th = d_th16 + ((size_t)b * TT + t0) * CI;

    float acc[2][8][4];
#pragma unroll
    for (int mi = 0; mi < 2; mi++)
#pragma unroll
        for (int nt = 0; nt < 8; nt++)
#pragma unroll
            for (int j = 0; j < 4; j++) acc[mi][nt][j] = 0.0f;

    const int lq = lane & 3, lr = lane >> 2;
    const int NC = 2;

    stage_h(smb, Mp, CI, 0, tid);
    stage_h(smb + TSZ * 4, Th, CI, 0, tid);
    CP_COMMIT();

    for (int kc = 0; kc < NC; kc++) {
        if (kc + 1 < NC) {
            uint32_t ab = smb + (uint32_t)(((kc + 1) & 1) * STGH) * 4;
            stage_h(ab, Mp, CI, (kc + 1) * 64, tid);
            stage_h(ab + TSZ * 4, Th, CI, (kc + 1) * 64, tid);
            CP_COMMIT();
            CP_WAIT1();
        } else {
            CP_WAIT0();
        }
        __syncthreads();
        const uint32_t* As = smem + (kc & 1) * STGH;
        const uint32_t* Bs = As + TSZ;
#pragma unroll
        for (int ks = 0; ks < 4; ks++) {
            int k0 = ks * 8;
            uint32_t a[2][4], bf[8][2];
#pragma unroll
            for (int mi = 0; mi < 2; mi++)
                ldA16(a[mi], As, (wo * 2 + mi) * 16, k0, lq, lr);
#pragma unroll
            for (int nt = 0; nt < 8; nt++) {
                int n = wt * 64 + nt * 8 + lr;
                bf[nt][0] = Bs[n * PIT + k0 + lq];
                bf[nt][1] = Bs[n * PIT + k0 + 4 + lq];
            }
#pragma unroll
            for (int mi = 0; mi < 2; mi++)
#pragma unroll
                for (int nt = 0; nt < 8; nt++)
                    mma_f16(acc[mi][nt], a[mi], bf[nt]);
        }
        __syncthreads();
    }

    float* wyp = d_wy + (size_t)b * CC * TT;
#pragma unroll
    for (int mi = 0; mi < 2; mi++) {
        int o1 = o0 + wo * 32 + mi * 16 + lr;
        int o2 = o1 + 8;
        float bz1 = wb[o1], bz2 = wb[o2];
        float s1 = 0.f, q1 = 0.f, s2 = 0.f, q2 = 0.f;
#pragma unroll
        for (int nt = 0; nt < 8; nt++) {
            int t = t0 + wt * 64 + nt * 8 + 2 * lq;
            float v0 = acc[mi][nt][0] + bz1, v1 = acc[mi][nt][1] + bz1;
            float v2 = acc[mi][nt][2] + bz2, v3 = acc[mi][nt][3] + bz2;
            s1 += v0 + v1; q1 = fmaf(v0, v0, q1); q1 = fmaf(v1, v1, q1);
            s2 += v2 + v3; q2 = fmaf(v2, v2, q2); q2 = fmaf(v3, v3, q2);
            *(float2*)(wyp + (size_t)o1 * TT + t) = make_float2(v0, v1);
            *(float2*)(wyp + (size_t)o2 * TT + t) = make_float2(v2, v3);
        }
#pragma unroll
        for (int off = 1; off < 4; off <<= 1) {
            s1 += __shfl_xor_sync(0xffffffffu, s1, off);
            q1 += __shfl_xor_sync(0xffffffffu, q1, off);
            s2 += __shfl_xor_sync(0xffffffffu, s2, off);
            q2 += __shfl_xor_sync(0xffffffffu, q2, off);
        }
        if (lq == 0) {
            atomicAdd(&d_sum[o1], s1);
            atomicAdd(&d_sumsq[o1], q1);
            atomicAdd(&d_sum[o2], s2);
            atomicAdd(&d_sumsq[o2], q2);
        }
    }
}

// ---------------------------------------------------------------------------
// K5: finalize BN statistics.
// ---------------------------------------------------------------------------
__global__ void k_stats(const float* __restrict__ gamma, const float* __restrict__ beta)
{
    int o = threadIdx.x;
    if (o < CC) {
        float mean = d_sum[o]   * (1.0f / BNT);
        float var  = d_sumsq[o] * (1.0f / BNT) - mean * mean;
        float sc   = gamma[o] * rsqrtf(var + 1e-5f);
        d_scale[o] = sc;
        d_shift[o] = beta[o] - mean * sc;
    }
}

// ---------------------------------------------------------------------------
// K6: out = scale[o]*wy + shift[o] + x
// ---------------------------------------------------------------------------
__global__ __launch_bounds__(256) void k_out(const float* __restrict__ x,
                                             float* __restrict__ out)
{
    size_t i4 = (size_t)blockIdx.x * 256 + threadIdx.x;
    int o = (int)((i4 >> 11) & 255);
    float sc = d_scale[o], sh = d_shift[o];
    float4 w  = *((const float4*)d_wy + i4);
    float4 xv = *((const float4*)x + i4);
    float4 r;
    r.x = fmaf(sc, w.x, sh) + xv.x;
    r.y = fmaf(sc, w.y, sh) + xv.y;
    r.z = fmaf(sc, w.z, sh) + xv.z;
    r.w = fmaf(sc, w.w, sh) + xv.w;
    ((float4*)out)[i4] = r;
}

// ---------------------------------------------------------------------------
// Launch: fork/join (graph-capturable).
//   s2            : init, wcvt                        -> eI
//   s0 (main)     : xt -> [eI] conv_th   ...          -> (tail)
//   s1 (high prio): [eX, eI] conv_pg -> S -> M        -> eJ
//   tail on s0    : [eJ] wy -> stats -> out
// ---------------------------------------------------------------------------
extern "C" void kernel_launch(void* const* d_in, const int* in_sizes, int n_in,
                              void* d_out, int out_size)
{
    const float* x     = (const float*)d_in[0];
    const float* tw    = (const float*)d_in[1];
    const float* tb    = (const float*)d_in[2];
    const float* pw    = (const float*)d_in[3];
    const float* pb    = (const float*)d_in[4];
    const float* gw    = (const float*)d_in[5];
    const float* gb    = (const float*)d_in[6];
    const float* ww    = (const float*)d_in[7];
    const float* wb    = (const float*)d_in[8];
    const float* gamma = (const float*)d_in[9];
    const float* beta  = (const float*)d_in[10];
    float* out = (float*)d_out;

    static cudaStream_t s1 = nullptr, s2 = nullptr;
    static cudaEvent_t eF = nullptr, eI = nullptr, eX = nullptr, eJ = nullptr;
    static int init_done = 0;
    if (!init_done) {
        cudaFuncSetAttribute(k_conv_th, cudaFuncAttributeMaxDynamicSharedMemorySize, SMEM16);
        cudaFuncSetAttribute(k_conv_pg, cudaFuncAttributeMaxDynamicSharedMemorySize, SMEM16);
        cudaFuncSetAttribute(k_S16,     cudaFuncAttributeMaxDynamicSharedMemorySize, SMEM16);
        cudaFuncSetAttribute(k_wy16,    cudaFuncAttributeMaxDynamicSharedMemorySize, SMEM16);
        int lo, hi;
        cudaDeviceGetStreamPriorityRange(&lo, &hi);
        cudaStreamCreateWithPriority(&s1, cudaStreamNonBlocking, hi);
        cudaStreamCreateWithPriority(&s2, cudaStreamNonBlocking, hi);
        cudaEventCreateWithFlags(&eF, cudaEventDisableTiming);
        cudaEventCreateWithFlags(&eI, cudaEventDisableTiming);
        cudaEventCreateWithFlags(&eX, cudaEventDisableTiming);
        cudaEventCreateWithFlags(&eJ, cudaEventDisableTiming);
        init_done = 1;
    }

    cudaEventRecord(eF, 0);
    cudaStreamWaitEvent(s1, eF, 0);
    cudaStreamWaitEvent(s2, eF, 0);

    // s2: zero accumulators + weight conversion.
    k_init<<<256, 256, 0, s2>>>();
    k_wcvt<<<384, 256, 0, s2>>>(tw, pw, gw);
    cudaEventRecord(eI, s2);

    // s0: transpose+convert x.
    k_xt<<<dim3(TT / 64, CC / 64, BB), 256, 0, 0>>>(x);
    cudaEventRecord(eX, 0);

    // s1: phi+g convs, then S, then M.
    cudaStreamWaitEvent(s1, eX, 0);
    cudaStreamWaitEvent(s1, eI, 0);
    k_conv_pg<<<dim3(TT / 128, 2, BB), 256, SMEM16, s1>>>(pb, gb);
    k_S16<<<dim3(16, BB), 256, SMEM16, s1>>>();
    k_M2f<<<128, 256, 0, s1>>>(ww);
    cudaEventRecord(eJ, s1);

    // s0: theta conv concurrently (after weights are converted).
    cudaStreamWaitEvent(0, eI, 0);
    k_conv_th<<<dim3(TT / 128, 1, BB), 256, SMEM16, 0>>>(tb);

    // Join, then dependent tail.
    cudaStreamWaitEvent(0, eJ, 0);
    k_wy16<<<dim3(TT / 128, 2, BB), 256, SMEM16, 0>>>(wb);
    k_stats<<<1, 256>>>(gamma, beta);
    k_out<<<8192, 256>>>(x, out);
}

// round 15
// speedup vs baseline: 1.2577x; 1.0400x over previous
#include <cuda_runtime.h>
#include <cuda_fp16.h>
#include <cstdint>

#define BB 4
#define CC 256
#define CI 128
#define TT 8192
#define NN 4096
#define BNT (BB*TT)

// Scratch (device globals; no allocation allowed). 16B-aligned for cp.async.
__device__ __align__(16) __half d_xt16[BB*TT*CC];  // x^T [b][t][c], 16 MB
__device__ __align__(16) __half d_w16[3*CI*CC];    // theta/phi/g weights fp16
__device__ __align__(16) __half d_th16[BB*TT*CI];  // theta^T [b][t][a], 8 MB
__device__ __align__(16) __half d_p16[BB*CI*NN];   // phi [b][ci][n], 4 MB
__device__ __align__(16) __half d_g16[BB*CI*NN];   // g   [b][ci][n], 4 MB
__device__ __align__(16) __half d_M16[BB*CC*CI];   // M [b][o][a] fp16
__device__ __align__(16) __half d_wy16[BB*CC*TT];  // wy fp16, 16 MB
__device__ float d_S[BB*CI*CI];
__device__ float d_sum[CC];
__device__ float d_sumsq[CC];
__device__ float d_scale[CC];
__device__ float d_shift[CC];

// ---------------- fp16 mma.sync (m16n8k16), fp32 accumulate -----------------
__device__ __forceinline__ void mma_f16(float* d, const uint32_t* a, const uint32_t* b) {
    asm("mma.sync.aligned.m16n8k16.row.col.f32.f16.f16.f32 "
        "{%0,%1,%2,%3}, {%4,%5,%6,%7}, {%8,%9}, {%0,%1,%2,%3};"
        : "+f"(d[0]), "+f"(d[1]), "+f"(d[2]), "+f"(d[3])
        : "r"(a[0]), "r"(a[1]), "r"(a[2]), "r"(a[3]), "r"(b[0]), "r"(b[1]));
}
// ldmatrix x4: four 8x8 b16 tiles, one address per lane.
__device__ __forceinline__ void ldsm4(uint32_t* r, uint32_t addr) {
    asm volatile("ldmatrix.sync.aligned.m8n8.x4.shared.b16 {%0,%1,%2,%3}, [%4];"
        : "=r"(r[0]), "=r"(r[1]), "=r"(r[2]), "=r"(r[3]) : "r"(addr));
}

// ---------------- cp.async helpers ------------------------------------------
__device__ __forceinline__ uint32_t smem_u32(const void* p) {
    uint32_t a;
    asm("{ .reg .u64 t; cvta.to.shared.u64 t, %1; cvt.u32.u64 %0, t; }" : "=r"(a) : "l"(p));
    return a;
}
__device__ __forceinline__ void cp16(uint32_t dst, const void* src) {
    asm volatile("cp.async.cg.shared.global [%0], [%1], 16;" :: "r"(dst), "l"(src));
}
#define CP_COMMIT() asm volatile("cp.async.commit_group;" ::: "memory")
#define CP_WAIT1()  asm volatile("cp.async.wait_group 1;" ::: "memory")
#define CP_WAIT0()  asm volatile("cp.async.wait_group 0;" ::: "memory")

// SMEM: per stage two fp16 tiles, 128 rows x 64 halves (32 u32), pitch 36 u32
// (144 B = 9 x 16B: the 8 rows of each LDSM phase hit distinct 16B banks).
#define PIT 36
#define TSZ (128*PIT)          // 4608 u32 per tile
#define STGH (2*TSZ)           // 9216 u32 per stage
#define SMEM16 (2*STGH*4)      // 73728 B

// Stage 128 rows x 64 halves from row-major fp16 src (ld = lds halves).
__device__ __forceinline__ void stage_h(uint32_t dstb, const __half* __restrict__ src,
                                        int lds, int koff, int tid) {
#pragma unroll
    for (int i = 0; i < 4; i++) {
        int fid = i * 256 + tid;        // 0..1023 16B-chunks
        int r = fid >> 3, q = fid & 7;
        cp16(dstb + (uint32_t)(r * PIT + q * 4) * 4,
             src + (size_t)r * lds + koff + q * 8);
    }
}

// ---------------------------------------------------------------------------
// Shared HMMA mainloop body (macro-free): runs NC chunks of k=64 halves from
// Asrc/Bsrc (both row-major, 128 rows, ld in halves), accumulating into
// acc[2][8][4]. ldmatrix fragment loads:
//   A x4 tiles: (rows g+0..7, klo), (g+8..15, klo), (g..7, khi), (g+8..15, khi)
//     lane l -> row (l&7)+((l>>3)&1)*8, koff (l>>4)*4 u32.
//   B x4 tiles for nt-pair (2j,2j+1): (n0..7, klo), (n0..7, khi),
//     (n8..15, klo), (n8..15, khi): lane l -> row (l>>4)*8+(l&7),
//     koff ((l>>3)&1)*4 -> regs {b[2j][0], b[2j][1], b[2j+1][0], b[2j+1][1]}.
// ---------------------------------------------------------------------------
__device__ __forceinline__ void hmma_loop(
    float acc[2][8][4], uint32_t smb,
    const __half* __restrict__ Asrc, int lda,
    const __half* __restrict__ Bsrc, int ldb,
    int NC, int tid)
{
    const int lane = tid & 31;
    const int warp = tid >> 5;
    const int wo = warp >> 1, wt = warp & 1;
    const uint32_t aoff =
        ((uint32_t)(((lane & 7) + ((lane >> 3) & 1) * 8) * PIT + (lane >> 4) * 4)) * 4;
    const uint32_t boff =
        ((uint32_t)(((lane >> 4) * 8 + (lane & 7)) * PIT + ((lane >> 3) & 1) * 4)) * 4;

    stage_h(smb, Asrc, lda, 0, tid);
    stage_h(smb + TSZ * 4, Bsrc, ldb, 0, tid);
    CP_COMMIT();

    for (int kc = 0; kc < NC; kc++) {
        if (kc + 1 < NC) {
            uint32_t ab = smb + (uint32_t)(((kc + 1) & 1) * STGH) * 4;
            stage_h(ab, Asrc, lda, (kc + 1) * 64, tid);
            stage_h(ab + TSZ * 4, Bsrc, ldb, (kc + 1) * 64, tid);
            CP_COMMIT();
            CP_WAIT1();
        } else {
            CP_WAIT0();
        }
        __syncthreads();
        const uint32_t As_b = smb + (uint32_t)((kc & 1) * STGH) * 4;
        const uint32_t Bs_b = As_b + TSZ * 4;
#pragma unroll
        for (int ks = 0; ks < 4; ks++) {
            uint32_t k04 = (uint32_t)ks * 32;   // 8 u32 per ks
            uint32_t a[2][4], bf[4][4];
            ldsm4(a[0], As_b + (uint32_t)((wo * 2 + 0) * 16 * PIT) * 4 + k04 + aoff);
            ldsm4(a[1], As_b + (uint32_t)((wo * 2 + 1) * 16 * PIT) * 4 + k04 + aoff);
#pragma unroll
            for (int j = 0; j < 4; j++)
                ldsm4(bf[j], Bs_b + (uint32_t)((wt * 64 + j * 16) * PIT) * 4 + k04 + boff);
#pragma unroll
            for (int mi = 0; mi < 2; mi++)
#pragma unroll
                for (int j = 0; j < 4; j++) {
                    mma_f16(acc[mi][2 * j],     a[mi], &bf[j][0]);
                    mma_f16(acc[mi][2 * j + 1], a[mi], &bf[j][2]);
                }
        }
        __syncthreads();
    }
}

// ---------------------------------------------------------------------------
// K0: zero accumulators.
// ---------------------------------------------------------------------------
__global__ void k_init() {
    int i = blockIdx.x * blockDim.x + threadIdx.x;   // 0..65535
    d_S[i] = 0.0f;
    if (i < CC) { d_sum[i] = 0.0f; d_sumsq[i] = 0.0f; }
}

// Convert the three 128x256 weight matrices to fp16 (packed [3][128][256]).
__global__ void k_wcvt(const float* __restrict__ tw, const float* __restrict__ pw,
                       const float* __restrict__ gw) {
    int i = blockIdx.x * 256 + threadIdx.x;          // grid 384
    const float* src = (i < CI*CC) ? tw : ((i < 2*CI*CC) ? pw : gw);
    d_w16[i] = __float2half(src[i & (CI*CC - 1)]);
}

// Transpose+convert x [b][c][t] fp32 -> d_xt16 [b][t][c] fp16. 64x64 tiles.
__global__ __launch_bounds__(256) void k_xt(const float* __restrict__ x) {
    __shared__ float sm[64][65];
    const int b = blockIdx.z, c0 = blockIdx.y * 64, t0 = blockIdx.x * 64;
    const float* xb = x + ((size_t)b * CC + c0) * TT + t0;
    const int tid = threadIdx.x;
#pragma unroll
    for (int i = 0; i < 4; i++) {
        int id = i * 256 + tid;
        int c = id >> 4, t4 = (id & 15) * 4;
        float4 v = *(const float4*)(xb + (size_t)c * TT + t4);
        sm[c][t4] = v.x; sm[c][t4+1] = v.y; sm[c][t4+2] = v.z; sm[c][t4+3] = v.w;
    }
    __syncthreads();
    __half* dst = d_xt16 + ((size_t)b * TT + t0) * CC + c0;
#pragma unroll
    for (int i = 0; i < 8; i++) {
        int id = i * 256 + tid;
        int t = id >> 5, cp = id & 31;
        *(__half2*)(dst + (size_t)t * CC + 2 * cp) =
            __floats2half2_rn(sm[2*cp][t], sm[2*cp+1][t]);
    }
}

// ---------------------------------------------------------------------------
// K1a: theta conv. A = x^T tile (M=t), B = W_theta (N=o). K=256 (4 chunks).
// Output theta^T fp16 [t][a].
// ---------------------------------------------------------------------------
__global__ void __launch_bounds__(256, 2) k_conv_th(const float* __restrict__ bt)
{
    extern __shared__ uint32_t smem[];
    const uint32_t smb = smem_u32(smem);
    const int tid = threadIdx.x;
    const int warp = tid >> 5, lane = tid & 31;
    const int wo = warp >> 1, wt = warp & 1;
    const int b  = blockIdx.z;
    const int t0 = blockIdx.x * 128;

    float acc[2][8][4];
#pragma unroll
    for (int mi = 0; mi < 2; mi++)
#pragma unroll
        for (int nt = 0; nt < 8; nt++)
#pragma unroll
            for (int j = 0; j < 4; j++) acc[mi][nt][j] = 0.0f;

    hmma_loop(acc, smb, d_xt16 + ((size_t)b * TT + t0) * CC, CC, d_w16, CC, 4, tid);

    const int lq = lane & 3, lr = lane >> 2;
    __half* dst = d_th16 + ((size_t)b * TT + t0) * CI;
#pragma unroll
    for (int mi = 0; mi < 2; mi++) {
        int t1 = wo * 32 + mi * 16 + lr;
        int t2 = t1 + 8;
#pragma unroll
        for (int nt = 0; nt < 8; nt++) {
            int o = wt * 64 + nt * 8 + 2 * lq;
            float b0 = bt[o], b1 = bt[o + 1];
            *(__half2*)(dst + (size_t)t1 * CI + o) =
                __floats2half2_rn(acc[mi][nt][0] + b0, acc[mi][nt][1] + b1);
            *(__half2*)(dst + (size_t)t2 * CI + o) =
                __floats2half2_rn(acc[mi][nt][2] + b0, acc[mi][nt][3] + b1);
        }
    }
}

// ---------------------------------------------------------------------------
// K1b: phi/g conv (blockIdx.y selects). A = W (M=o), B = x^T (N=t); maxpool
// over in-thread t-pair. Output fp16 [ci][n].
// ---------------------------------------------------------------------------
__global__ void __launch_bounds__(256, 2) k_conv_pg(const float* __restrict__ pb,
                                                    const float* __restrict__ gb)
{
    extern __shared__ uint32_t smem[];
    const uint32_t smb = smem_u32(smem);
    const int tid = threadIdx.x;
    const int warp = tid >> 5, lane = tid & 31;
    const int wo = warp >> 1, wt = warp & 1;
    const int b  = blockIdx.z;
    const int w  = blockIdx.y;               // 0 = phi, 1 = g
    const int t0 = blockIdx.x * 128;
    const float* bias = (w == 0) ? pb : gb;

    float acc[2][8][4];
#pragma unroll
    for (int mi = 0; mi < 2; mi++)
#pragma unroll
        for (int nt = 0; nt < 8; nt++)
#pragma unroll
            for (int j = 0; j < 4; j++) acc[mi][nt][j] = 0.0f;

    hmma_loop(acc, smb, d_w16 + (size_t)(1 + w) * CI * CC, CC,
              d_xt16 + ((size_t)b * TT + t0) * CC, CC, 4, tid);

    const int lq = lane & 3, lr = lane >> 2;
    __half* dst = ((w == 0) ? d_p16 : d_g16) + (size_t)b * CI * NN + (t0 >> 1);
#pragma unroll
    for (int mi = 0; mi < 2; mi++) {
        int o1 = wo * 32 + mi * 16 + lr;
        int o2 = o1 + 8;
        float bz1 = bias[o1], bz2 = bias[o2];
#pragma unroll
        for (int nt = 0; nt < 8; nt++) {
            int np = wt * 32 + nt * 4 + lq;
            dst[(size_t)o1 * NN + np] =
                __float2half(fmaxf(acc[mi][nt][0], acc[mi][nt][1]) + bz1);
            dst[(size_t)o2 * NN + np] =
                __float2half(fmaxf(acc[mi][nt][2], acc[mi][nt][3]) + bz2);
        }
    }
}

// ---------------------------------------------------------------------------
// K2: S = phi . g^T. Split-K: 16 slabs of 256 n (4 chunks). fp32 atomics.
// ---------------------------------------------------------------------------
__global__ void __launch_bounds__(256, 2) k_S16()
{
    extern __shared__ uint32_t smem[];
    const uint32_t smb = smem_u32(smem);
    const int tid = threadIdx.x;
    const int warp = tid >> 5, lane = tid & 31;
    const int wo = warp >> 1, wt = warp & 1;
    const int b  = blockIdx.y;
    const int n0 = blockIdx.x * 256;

    float acc[2][8][4];
#pragma unroll
    for (int mi = 0; mi < 2; mi++)
#pragma unroll
        for (int nt = 0; nt < 8; nt++)
#pragma unroll
            for (int j = 0; j < 4; j++) acc[mi][nt][j] = 0.0f;

    hmma_loop(acc, smb, d_p16 + (size_t)b * CI * NN + n0, NN,
              d_g16 + (size_t)b * CI * NN + n0, NN, 4, tid);

    const int lq = lane & 3, lr = lane >> 2;
    float* Sp = d_S + (size_t)b * CI * CI;
#pragma unroll
    for (int mi = 0; mi < 2; mi++) {
        int a1 = wo * 32 + mi * 16 + lr;
        int a2 = a1 + 8;
#pragma unroll
        for (int nt = 0; nt < 8; nt++) {
            int ci = wt * 64 + nt * 8 + 2 * lq;
            atomicAdd(&Sp[(size_t)a1 * CI + ci],     acc[mi][nt][0]);
            atomicAdd(&Sp[(size_t)a1 * CI + ci + 1], acc[mi][nt][1]);
            atomicAdd(&Sp[(size_t)a2 * CI + ci],     acc[mi][nt][2]);
            atomicAdd(&Sp[(size_t)a2 * CI + ci + 1], acc[mi][nt][3]);
        }
    }
}

// NOTE: hmma_loop stages both operands with 128 rows; S uses row slices at
// offset n0 (phi/g are [ci][n], ld = NN): A rows are the 128 ci of phi,
// B rows the 128 ci of g — both full. k offset = n. Correct as in R14.

// ---------------------------------------------------------------------------
// K3: M[b,o,a] = (1/N) sum_k ww[o,k] S[b,a,k]; fp32 SIMT, writes fp16 M.
// ---------------------------------------------------------------------------
__global__ __launch_bounds__(256) void k_M2f(const float* __restrict__ ww)
{
    __shared__ float ws[32][129];
    __shared__ float ss[32][129];

    const int tid = threadIdx.x;
    const int b  = blockIdx.x >> 5;
    const int ob = (blockIdx.x >> 2) & 7;
    const int ab = blockIdx.x & 3;

#pragma unroll
    for (int i = 0; i < 4; i++) {
        int fid = i * 256 + tid;
        int r = fid >> 5, c4 = fid & 31;
        float4 v = *(const float4*)(ww + (size_t)(ob * 32 + r) * CI + 4 * c4);
        ws[r][4*c4+0] = v.x; ws[r][4*c4+1] = v.y; ws[r][4*c4+2] = v.z; ws[r][4*c4+3] = v.w;
        float4 u = *(const float4*)(d_S + (size_t)b * CI * CI + (size_t)(ab * 32 + r) * CI + 4 * c4);
        ss[r][4*c4+0] = u.x; ss[r][4*c4+1] = u.y; ss[r][4*c4+2] = u.z; ss[r][4*c4+3] = u.w;
    }
    __syncthreads();

    const int ty = tid >> 3;
    const int tx = tid & 7;
    float acc[4] = {0.f, 0.f, 0.f, 0.f};
#pragma unroll
    for (int k = 0; k < CI; k++) {
        float wv = ws[ty][k];
#pragma unroll
        for (int j = 0; j < 4; j++) acc[j] = fmaf(wv, ss[4*tx+j][k], acc[j]);
    }
    const float invN = 1.0f / NN;
    __half* Mp = d_M16 + (size_t)b * CC * CI + (size_t)(ob * 32 + ty) * CI + ab * 32 + 4 * tx;
#pragma unroll
    for (int j = 0; j < 4; j++) Mp[j] = __float2half(acc[j] * invN);
}

// ---------------------------------------------------------------------------
// K4: wy = M16 . theta^T + w_b (fp16 mma); writes fp16 wy; BN sums from the
// ROUNDED values so stats match exactly what k_out scales.
// ---------------------------------------------------------------------------
__global__ void __launch_bounds__(256, 2) k_wy16(const float* __restrict__ wb)
{
    extern __shared__ uint32_t smem[];
    const uint32_t smb = smem_u32(smem);
    const int tid = threadIdx.x;
    const int warp = tid >> 5, lane = tid & 31;
    const int wo = warp >> 1, wt = warp & 1;
    const int b  = blockIdx.z;
    const int o0 = blockIdx.y * 128;
    const int t0 = blockIdx.x * 128;

    float acc[2][8][4];
#pragma unroll
    for (int mi = 0; mi < 2; mi++)
#pragma unroll
        for (int nt = 0; nt < 8; nt++)
#pragma unroll
            for (int j = 0; j < 4; j++) acc[mi][nt][j] = 0.0f;

    hmma_loop(acc, smb, d_M16 + ((size_t)b * CC + o0) * CI, CI,
              d_th16 + ((size_t)b * TT + t0) * CI, CI, 2, tid);

    const int lq = lane & 3, lr = lane >> 2;
    __half* wyp = d_wy16 + (size_t)b * CC * TT;
#pragma unroll
    for (int mi = 0; mi < 2; mi++) {
        int o1 = o0 + wo * 32 + mi * 16 + lr;
        int o2 = o1 + 8;
        float bz1 = wb[o1], bz2 = wb[o2];
        float s1 = 0.f, q1 = 0.f, s2 = 0.f, q2 = 0.f;
#pragma unroll
        for (int nt = 0; nt < 8; nt++) {
            int t = t0 + wt * 64 + nt * 8 + 2 * lq;
            __half2 h1 = __floats2half2_rn(acc[mi][nt][0] + bz1, acc[mi][nt][1] + bz1);
            __half2 h2 = __floats2half2_rn(acc[mi][nt][2] + bz2, acc[mi][nt][3] + bz2);
            *(__half2*)(wyp + (size_t)o1 * TT + t) = h1;
            *(__half2*)(wyp + (size_t)o2 * TT + t) = h2;
            float2 f1 = __half22float2(h1), f2 = __half22float2(h2);
            s1 += f1.x + f1.y; q1 = fmaf(f1.x, f1.x, q1); q1 = fmaf(f1.y, f1.y, q1);
            s2 += f2.x + f2.y; q2 = fmaf(f2.x, f2.x, q2); q2 = fmaf(f2.y, f2.y, q2);
        }
#pragma unroll
        for (int off = 1; off < 4; off <<= 1) {
            s1 += __shfl_xor_sync(0xffffffffu, s1, off);
            q1 += __shfl_xor_sync(0xffffffffu, q1, off);
            s2 += __shfl_xor_sync(0xffffffffu, s2, off);
            q2 += __shfl_xor_sync(0xffffffffu, q2, off);
        }
        if (lq == 0) {
            atomicAdd(&d_sum[o1], s1);
            atomicAdd(&d_sumsq[o1], q1);
            atomicAdd(&d_sum[o2], s2);
            atomicAdd(&d_sumsq[o2], q2);
        }
    }
}

// ---------------------------------------------------------------------------
// K5: finalize BN statistics.
// ---------------------------------------------------------------------------
__global__ void k_stats(const float* __restrict__ gamma, const float* __restrict__ beta)
{
    int o = threadIdx.x;
    if (o < CC) {
        float mean = d_sum[o]   * (1.0f / BNT);
        float var  = d_sumsq[o] * (1.0f / BNT) - mean * mean;
        float sc   = gamma[o] * rsqrtf(var + 1e-5f);
        d_scale[o] = sc;
        d_shift[o] = beta[o] - mean * sc;
    }
}

// ---------------------------------------------------------------------------
// K6: out = scale[o]*wy16 + shift[o] + x
// ---------------------------------------------------------------------------
__global__ __launch_bounds__(256) void k_out(const float* __restrict__ x,
                                             float* __restrict__ out)
{
    size_t i4 = (size_t)blockIdx.x * 256 + threadIdx.x;   // 4 elements
    int o = (int)((i4 >> 11) & 255);
    float sc = d_scale[o], sh = d_shift[o];
    const __half2* w2 = (const __half2*)d_wy16;
    float2 f0 = __half22float2(w2[i4 * 2]);
    float2 f1 = __half22float2(w2[i4 * 2 + 1]);
    float4 xv = *((const float4*)x + i4);
    float4 r;
    r.x = fmaf(sc, f0.x, sh) + xv.x;
    r.y = fmaf(sc, f0.y, sh) + xv.y;
    r.z = fmaf(sc, f1.x, sh) + xv.z;
    r.w = fmaf(sc, f1.y, sh) + xv.w;
    ((float4*)out)[i4] = r;
}

// ---------------------------------------------------------------------------
// Launch: fork/join (graph-capturable).
// ---------------------------------------------------------------------------
extern "C" void kernel_launch(void* const* d_in, const int* in_sizes, int n_in,
                              void* d_out, int out_size)
{
    const float* x     = (const float*)d_in[0];
    const float* tw    = (const float*)d_in[1];
    const float* tb    = (const float*)d_in[2];
    const float* pw    = (const float*)d_in[3];
    const float* pb    = (const float*)d_in[4];
    const float* gw    = (const float*)d_in[5];
    const float* gb    = (const float*)d_in[6];
    const float* ww    = (const float*)d_in[7];
    const float* wb    = (const float*)d_in[8];
    const float* gamma = (const float*)d_in[9];
    const float* beta  = (const float*)d_in[10];
    float* out = (float*)d_out;

    static cudaStream_t s1 = nullptr, s2 = nullptr;
    static cudaEvent_t eF = nullptr, eI = nullptr, eX = nullptr, eJ = nullptr;
    static int init_done = 0;
    if (!init_done) {
        cudaFuncSetAttribute(k_conv_th, cudaFuncAttributeMaxDynamicSharedMemorySize, SMEM16);
        cudaFuncSetAttribute(k_conv_pg, cudaFuncAttributeMaxDynamicSharedMemorySize, SMEM16);
        cudaFuncSetAttribute(k_S16,     cudaFuncAttributeMaxDynamicSharedMemorySize, SMEM16);
        cudaFuncSetAttribute(k_wy16,    cudaFuncAttributeMaxDynamicSharedMemorySize, SMEM16);
        int lo, hi;
        cudaDeviceGetStreamPriorityRange(&lo, &hi);
        cudaStreamCreateWithPriority(&s1, cudaStreamNonBlocking, hi);
        cudaStreamCreateWithPriority(&s2, cudaStreamNonBlocking, hi);
        cudaEventCreateWithFlags(&eF, cudaEventDisableTiming);
        cudaEventCreateWithFlags(&eI, cudaEventDisableTiming);
        cudaEventCreateWithFlags(&eX, cudaEventDisableTiming);
        cudaEventCreateWithFlags(&eJ, cudaEventDisableTiming);
        init_done = 1;
    }

    cudaEventRecord(eF, 0);
    cudaStreamWaitEvent(s1, eF, 0);
    cudaStreamWaitEvent(s2, eF, 0);

    // s2: zero accumulators + weight conversion.
    k_init<<<256, 256, 0, s2>>>();
    k_wcvt<<<384, 256, 0, s2>>>(tw, pw, gw);
    cudaEventRecord(eI, s2);

    // s0: transpose+convert x.
    k_xt<<<dim3(TT / 64, CC / 64, BB), 256, 0, 0>>>(x);
    cudaEventRecord(eX, 0);

    // s1: phi+g convs, then S, then M.
    cudaStreamWaitEvent(s1, eX, 0);
    cudaStreamWaitEvent(s1, eI, 0);
    k_conv_pg<<<dim3(TT / 128, 2, BB), 256, SMEM16, s1>>>(pb, gb);
    k_S16<<<dim3(16, BB), 256, SMEM16, s1>>>();
    k_M2f<<<128, 256, 0, s1>>>(ww);
    cudaEventRecord(eJ, s1);

    // s0: theta conv concurrently (after weights are converted).
    cudaStreamWaitEvent(0, eI, 0);
    k_conv_th<<<dim3(TT / 128, 1, BB), 256, SMEM16, 0>>>(tb);

    // Join, then dependent tail.
    cudaStreamWaitEvent(0, eJ, 0);
    k_wy16<<<dim3(TT / 128, 2, BB), 256, SMEM16, 0>>>(wb);
    k_stats<<<1, 256>>>(gamma, beta);
    k_out<<<8192, 256>>>(x, out);
}

// round 16
// speedup vs baseline: 1.2858x; 1.0223x over previous
#include <cuda_runtime.h>
#include <cuda_fp16.h>
#include <cstdint>

#define BB 4
#define CC 256
#define CI 128
#define TT 8192
#define NN 4096
#define BNT (BB*TT)

// Scratch (device globals; no allocation allowed). 16B-aligned for cp.async.
__device__ __align__(16) __half d_xt16[BB*TT*CC];  // x^T [b][t][c], 16 MB
__device__ __align__(16) __half d_w16[3*CI*CC];    // theta/phi/g weights fp16
__device__ __align__(16) __half d_th16[BB*TT*CI];  // theta^T [b][t][a], 8 MB
__device__ __align__(16) __half d_p16[BB*CI*NN];   // phi [b][ci][n], 4 MB
__device__ __align__(16) __half d_g16[BB*CI*NN];   // g   [b][ci][n], 4 MB
__device__ __align__(16) __half d_M16[BB*CC*CI];   // M [b][o][a] fp16
__device__ __align__(16) __half d_wy16[BB*CC*TT];  // wy fp16, 16 MB
__device__ float d_S[BB*CI*CI];
__device__ float d_sum[CC];
__device__ float d_sumsq[CC];

// ---------------- fp16 mma.sync (m16n8k16), fp32 accumulate -----------------
__device__ __forceinline__ void mma_f16(float* d, const uint32_t* a, const uint32_t* b) {
    asm("mma.sync.aligned.m16n8k16.row.col.f32.f16.f16.f32 "
        "{%0,%1,%2,%3}, {%4,%5,%6,%7}, {%8,%9}, {%0,%1,%2,%3};"
        : "+f"(d[0]), "+f"(d[1]), "+f"(d[2]), "+f"(d[3])
        : "r"(a[0]), "r"(a[1]), "r"(a[2]), "r"(a[3]), "r"(b[0]), "r"(b[1]));
}
// ldmatrix x4: four 8x8 b16 tiles, one address per lane.
__device__ __forceinline__ void ldsm4(uint32_t* r, uint32_t addr) {
    asm volatile("ldmatrix.sync.aligned.m8n8.x4.shared.b16 {%0,%1,%2,%3}, [%4];"
        : "=r"(r[0]), "=r"(r[1]), "=r"(r[2]), "=r"(r[3]) : "r"(addr));
}

// ---------------- cp.async helpers ------------------------------------------
__device__ __forceinline__ uint32_t smem_u32(const void* p) {
    uint32_t a;
    asm("{ .reg .u64 t; cvta.to.shared.u64 t, %1; cvt.u32.u64 %0, t; }" : "=r"(a) : "l"(p));
    return a;
}
__device__ __forceinline__ void cp16(uint32_t dst, const void* src) {
    asm volatile("cp.async.cg.shared.global [%0], [%1], 16;" :: "r"(dst), "l"(src));
}
#define CP_COMMIT() asm volatile("cp.async.commit_group;" ::: "memory")
#define CP_WAIT1()  asm volatile("cp.async.wait_group 1;" ::: "memory")
#define CP_WAIT0()  asm volatile("cp.async.wait_group 0;" ::: "memory")

// SMEM: per stage two fp16 tiles, 128 rows x 64 halves (32 u32), pitch 36 u32
// (144 B = 9 x 16B: the 8 rows of each LDSM phase hit distinct 16B banks).
#define PIT 36
#define TSZ (128*PIT)          // 4608 u32 per tile
#define STGH (2*TSZ)           // 9216 u32 per stage
#define SMEM16 (2*STGH*4)      // 73728 B

// Stage 128 rows x 64 halves from row-major fp16 src (ld = lds halves).
__device__ __forceinline__ void stage_h(uint32_t dstb, const __half* __restrict__ src,
                                        int lds, int koff, int tid) {
#pragma unroll
    for (int i = 0; i < 4; i++) {
        int fid = i * 256 + tid;        // 0..1023 16B-chunks
        int r = fid >> 3, q = fid & 7;
        cp16(dstb + (uint32_t)(r * PIT + q * 4) * 4,
             src + (size_t)r * lds + koff + q * 8);
    }
}

// ---------------------------------------------------------------------------
// Shared HMMA mainloop. Warps differing in wo (SMSP partners) process the
// 4 k-steps of each chunk in rotated order to desynchronize LDSM bursts
// (accumulation-order change only).
// ---------------------------------------------------------------------------
__device__ __forceinline__ void hmma_loop(
    float acc[2][8][4], uint32_t smb,
    const __half* __restrict__ Asrc, int lda,
    const __half* __restrict__ Bsrc, int ldb,
    int NC, int tid)
{
    const int lane = tid & 31;
    const int warp = tid >> 5;
    const int wo = warp >> 1, wt = warp & 1;
    const uint32_t aoff =
        ((uint32_t)(((lane & 7) + ((lane >> 3) & 1) * 8) * PIT + (lane >> 4) * 4)) * 4;
    const uint32_t boff =
        ((uint32_t)(((lane >> 4) * 8 + (lane & 7)) * PIT + ((lane >> 3) & 1) * 4)) * 4;

    stage_h(smb, Asrc, lda, 0, tid);
    stage_h(smb + TSZ * 4, Bsrc, ldb, 0, tid);
    CP_COMMIT();

    for (int kc = 0; kc < NC; kc++) {
        if (kc + 1 < NC) {
            uint32_t ab = smb + (uint32_t)(((kc + 1) & 1) * STGH) * 4;
            stage_h(ab, Asrc, lda, (kc + 1) * 64, tid);
            stage_h(ab + TSZ * 4, Bsrc, ldb, (kc + 1) * 64, tid);
            CP_COMMIT();
            CP_WAIT1();
        } else {
            CP_WAIT0();
        }
        __syncthreads();
        const uint32_t As_b = smb + (uint32_t)((kc & 1) * STGH) * 4;
        const uint32_t Bs_b = As_b + TSZ * 4;
#pragma unroll
        for (int ks = 0; ks < 4; ks++) {
            int kss = (ks + wo) & 3;            // per-SMSP-partner rotation
            uint32_t k04 = (uint32_t)kss * 32;  // 8 u32 per ks
            uint32_t a[2][4], bf[4][4];
            ldsm4(a[0], As_b + (uint32_t)((wo * 2 + 0) * 16 * PIT) * 4 + k04 + aoff);
            ldsm4(a[1], As_b + (uint32_t)((wo * 2 + 1) * 16 * PIT) * 4 + k04 + aoff);
#pragma unroll
            for (int j = 0; j < 4; j++)
                ldsm4(bf[j], Bs_b + (uint32_t)((wt * 64 + j * 16) * PIT) * 4 + k04 + boff);
#pragma unroll
            for (int mi = 0; mi < 2; mi++)
#pragma unroll
                for (int j = 0; j < 4; j++) {
                    mma_f16(acc[mi][2 * j],     a[mi], &bf[j][0]);
                    mma_f16(acc[mi][2 * j + 1], a[mi], &bf[j][2]);
                }
        }
        __syncthreads();
    }
}

// ---------------------------------------------------------------------------
// K0: zero accumulators.
// ---------------------------------------------------------------------------
__global__ void k_init() {
    int i = blockIdx.x * blockDim.x + threadIdx.x;   // 0..65535
    d_S[i] = 0.0f;
    if (i < CC) { d_sum[i] = 0.0f; d_sumsq[i] = 0.0f; }
}

// Convert the three 128x256 weight matrices to fp16 (packed [3][128][256]).
__global__ void k_wcvt(const float* __restrict__ tw, const float* __restrict__ pw,
                       const float* __restrict__ gw) {
    int i = blockIdx.x * 256 + threadIdx.x;          // grid 384
    const float* src = (i < CI*CC) ? tw : ((i < 2*CI*CC) ? pw : gw);
    d_w16[i] = __float2half(src[i & (CI*CC - 1)]);
}

// Transpose+convert x [b][c][t] fp32 -> d_xt16 [b][t][c] fp16. 64x64 tiles.
__global__ __launch_bounds__(256) void k_xt(const float* __restrict__ x) {
    __shared__ float sm[64][65];
    const int b = blockIdx.z, c0 = blockIdx.y * 64, t0 = blockIdx.x * 64;
    const float* xb = x + ((size_t)b * CC + c0) * TT + t0;
    const int tid = threadIdx.x;
#pragma unroll
    for (int i = 0; i < 4; i++) {
        int id = i * 256 + tid;
        int c = id >> 4, t4 = (id & 15) * 4;
        float4 v = *(const float4*)(xb + (size_t)c * TT + t4);
        sm[c][t4] = v.x; sm[c][t4+1] = v.y; sm[c][t4+2] = v.z; sm[c][t4+3] = v.w;
    }
    __syncthreads();
    __half* dst = d_xt16 + ((size_t)b * TT + t0) * CC + c0;
#pragma unroll
    for (int i = 0; i < 8; i++) {
        int id = i * 256 + tid;
        int t = id >> 5, cp = id & 31;
        *(__half2*)(dst + (size_t)t * CC + 2 * cp) =
            __floats2half2_rn(sm[2*cp][t], sm[2*cp+1][t]);
    }
}

// ---------------------------------------------------------------------------
// K1a: theta conv. A = x^T tile (M=t), B = W_theta (N=o). K=256 (4 chunks).
// Output theta^T fp16 [t][a].
// ---------------------------------------------------------------------------
__global__ void __launch_bounds__(256, 2) k_conv_th(const float* __restrict__ bt)
{
    extern __shared__ uint32_t smem[];
    const uint32_t smb = smem_u32(smem);
    const int tid = threadIdx.x;
    const int warp = tid >> 5, lane = tid & 31;
    const int wo = warp >> 1, wt = warp & 1;
    const int b  = blockIdx.z;
    const int t0 = blockIdx.x * 128;

    float acc[2][8][4];
#pragma unroll
    for (int mi = 0; mi < 2; mi++)
#pragma unroll
        for (int nt = 0; nt < 8; nt++)
#pragma unroll
            for (int j = 0; j < 4; j++) acc[mi][nt][j] = 0.0f;

    hmma_loop(acc, smb, d_xt16 + ((size_t)b * TT + t0) * CC, CC, d_w16, CC, 4, tid);

    const int lq = lane & 3, lr = lane >> 2;
    __half* dst = d_th16 + ((size_t)b * TT + t0) * CI;
#pragma unroll
    for (int mi = 0; mi < 2; mi++) {
        int t1 = wo * 32 + mi * 16 + lr;
        int t2 = t1 + 8;
#pragma unroll
        for (int nt = 0; nt < 8; nt++) {
            int o = wt * 64 + nt * 8 + 2 * lq;
            float b0 = bt[o], b1 = bt[o + 1];
            *(__half2*)(dst + (size_t)t1 * CI + o) =
                __floats2half2_rn(acc[mi][nt][0] + b0, acc[mi][nt][1] + b1);
            *(__half2*)(dst + (size_t)t2 * CI + o) =
                __floats2half2_rn(acc[mi][nt][2] + b0, acc[mi][nt][3] + b1);
        }
    }
}

// ---------------------------------------------------------------------------
// K1b: phi/g conv (blockIdx.y selects). A = W (M=o), B = x^T (N=t); maxpool
// over in-thread t-pair. Output fp16 [ci][n].
// ---------------------------------------------------------------------------
__global__ void __launch_bounds__(256, 2) k_conv_pg(const float* __restrict__ pb,
                                                    const float* __restrict__ gb)
{
    extern __shared__ uint32_t smem[];
    const uint32_t smb = smem_u32(smem);
    const int tid = threadIdx.x;
    const int warp = tid >> 5, lane = tid & 31;
    const int wo = warp >> 1, wt = warp & 1;
    const int b  = blockIdx.z;
    const int w  = blockIdx.y;               // 0 = phi, 1 = g
    const int t0 = blockIdx.x * 128;
    const float* bias = (w == 0) ? pb : gb;

    float acc[2][8][4];
#pragma unroll
    for (int mi = 0; mi < 2; mi++)
#pragma unroll
        for (int nt = 0; nt < 8; nt++)
#pragma unroll
            for (int j = 0; j < 4; j++) acc[mi][nt][j] = 0.0f;

    hmma_loop(acc, smb, d_w16 + (size_t)(1 + w) * CI * CC, CC,
              d_xt16 + ((size_t)b * TT + t0) * CC, CC, 4, tid);

    const int lq = lane & 3, lr = lane >> 2;
    __half* dst = ((w == 0) ? d_p16 : d_g16) + (size_t)b * CI * NN + (t0 >> 1);
#pragma unroll
    for (int mi = 0; mi < 2; mi++) {
        int o1 = wo * 32 + mi * 16 + lr;
        int o2 = o1 + 8;
        float bz1 = bias[o1], bz2 = bias[o2];
#pragma unroll
        for (int nt = 0; nt < 8; nt++) {
            int np = wt * 32 + nt * 4 + lq;
            dst[(size_t)o1 * NN + np] =
                __float2half(fmaxf(acc[mi][nt][0], acc[mi][nt][1]) + bz1);
            dst[(size_t)o2 * NN + np] =
                __float2half(fmaxf(acc[mi][nt][2], acc[mi][nt][3]) + bz2);
        }
    }
}

// ---------------------------------------------------------------------------
// K2: S = phi . g^T. Split-K: 16 slabs of 256 n (4 chunks). fp32 atomics.
// ---------------------------------------------------------------------------
__global__ void __launch_bounds__(256, 2) k_S16()
{
    extern __shared__ uint32_t smem[];
    const uint32_t smb = smem_u32(smem);
    const int tid = threadIdx.x;
    const int warp = tid >> 5, lane = tid & 31;
    const int wo = warp >> 1, wt = warp & 1;
    const int b  = blockIdx.y;
    const int n0 = blockIdx.x * 256;

    float acc[2][8][4];
#pragma unroll
    for (int mi = 0; mi < 2; mi++)
#pragma unroll
        for (int nt = 0; nt < 8; nt++)
#pragma unroll
            for (int j = 0; j < 4; j++) acc[mi][nt][j] = 0.0f;

    hmma_loop(acc, smb, d_p16 + (size_t)b * CI * NN + n0, NN,
              d_g16 + (size_t)b * CI * NN + n0, NN, 4, tid);

    const int lq = lane & 3, lr = lane >> 2;
    float* Sp = d_S + (size_t)b * CI * CI;
#pragma unroll
    for (int mi = 0; mi < 2; mi++) {
        int a1 = wo * 32 + mi * 16 + lr;
        int a2 = a1 + 8;
#pragma unroll
        for (int nt = 0; nt < 8; nt++) {
            int ci = wt * 64 + nt * 8 + 2 * lq;
            atomicAdd(&Sp[(size_t)a1 * CI + ci],     acc[mi][nt][0]);
            atomicAdd(&Sp[(size_t)a1 * CI + ci + 1], acc[mi][nt][1]);
            atomicAdd(&Sp[(size_t)a2 * CI + ci],     acc[mi][nt][2]);
            atomicAdd(&Sp[(size_t)a2 * CI + ci + 1], acc[mi][nt][3]);
        }
    }
}

// ---------------------------------------------------------------------------
// K3: M[b,o,a] = (1/N) sum_k ww[o,k] S[b,a,k]; fp32 SIMT, writes fp16 M.
// ---------------------------------------------------------------------------
__global__ __launch_bounds__(256) void k_M2f(const float* __restrict__ ww)
{
    __shared__ float ws[32][129];
    __shared__ float ss[32][129];

    const int tid = threadIdx.x;
    const int b  = blockIdx.x >> 5;
    const int ob = (blockIdx.x >> 2) & 7;
    const int ab = blockIdx.x & 3;

#pragma unroll
    for (int i = 0; i < 4; i++) {
        int fid = i * 256 + tid;
        int r = fid >> 5, c4 = fid & 31;
        float4 v = *(const float4*)(ww + (size_t)(ob * 32 + r) * CI + 4 * c4);
        ws[r][4*c4+0] = v.x; ws[r][4*c4+1] = v.y; ws[r][4*c4+2] = v.z; ws[r][4*c4+3] = v.w;
        float4 u = *(const float4*)(d_S + (size_t)b * CI * CI + (size_t)(ab * 32 + r) * CI + 4 * c4);
        ss[r][4*c4+0] = u.x; ss[r][4*c4+1] = u.y; ss[r][4*c4+2] = u.z; ss[r][4*c4+3] = u.w;
    }
    __syncthreads();

    const int ty = tid >> 3;
    const int tx = tid & 7;
    float acc[4] = {0.f, 0.f, 0.f, 0.f};
#pragma unroll
    for (int k = 0; k < CI; k++) {
        float wv = ws[ty][k];
#pragma unroll
        for (int j = 0; j < 4; j++) acc[j] = fmaf(wv, ss[4*tx+j][k], acc[j]);
    }
    const float invN = 1.0f / NN;
    __half* Mp = d_M16 + (size_t)b * CC * CI + (size_t)(ob * 32 + ty) * CI + ab * 32 + 4 * tx;
#pragma unroll
    for (int j = 0; j < 4; j++) Mp[j] = __float2half(acc[j] * invN);
}

// ---------------------------------------------------------------------------
// K4: wy = M16 . theta^T + w_b (fp16 mma); writes fp16 wy; BN sums from the
// ROUNDED values so stats match exactly what k_out scales.
// ---------------------------------------------------------------------------
__global__ void __launch_bounds__(256, 2) k_wy16(const float* __restrict__ wb)
{
    extern __shared__ uint32_t smem[];
    const uint32_t smb = smem_u32(smem);
    const int tid = threadIdx.x;
    const int warp = tid >> 5, lane = tid & 31;
    const int wo = warp >> 1, wt = warp & 1;
    const int b  = blockIdx.z;
    const int o0 = blockIdx.y * 128;
    const int t0 = blockIdx.x * 128;

    float acc[2][8][4];
#pragma unroll
    for (int mi = 0; mi < 2; mi++)
#pragma unroll
        for (int nt = 0; nt < 8; nt++)
#pragma unroll
            for (int j = 0; j < 4; j++) acc[mi][nt][j] = 0.0f;

    hmma_loop(acc, smb, d_M16 + ((size_t)b * CC + o0) * CI, CI,
              d_th16 + ((size_t)b * TT + t0) * CI, CI, 2, tid);

    const int lq = lane & 3, lr = lane >> 2;
    __half* wyp = d_wy16 + (size_t)b * CC * TT;
#pragma unroll
    for (int mi = 0; mi < 2; mi++) {
        int o1 = o0 + wo * 32 + mi * 16 + lr;
        int o2 = o1 + 8;
        float bz1 = wb[o1], bz2 = wb[o2];
        float s1 = 0.f, q1 = 0.f, s2 = 0.f, q2 = 0.f;
#pragma unroll
        for (int nt = 0; nt < 8; nt++) {
            int t = t0 + wt * 64 + nt * 8 + 2 * lq;
            __half2 h1 = __floats2half2_rn(acc[mi][nt][0] + bz1, acc[mi][nt][1] + bz1);
            __half2 h2 = __floats2half2_rn(acc[mi][nt][2] + bz2, acc[mi][nt][3] + bz2);
            *(__half2*)(wyp + (size_t)o1 * TT + t) = h1;
            *(__half2*)(wyp + (size_t)o2 * TT + t) = h2;
            float2 f1 = __half22float2(h1), f2 = __half22float2(h2);
            s1 += f1.x + f1.y; q1 = fmaf(f1.x, f1.x, q1); q1 = fmaf(f1.y, f1.y, q1);
            s2 += f2.x + f2.y; q2 = fmaf(f2.x, f2.x, q2); q2 = fmaf(f2.y, f2.y, q2);
        }
#pragma unroll
        for (int off = 1; off < 4; off <<= 1) {
            s1 += __shfl_xor_sync(0xffffffffu, s1, off);
            q1 += __shfl_xor_sync(0xffffffffu, q1, off);
            s2 += __shfl_xor_sync(0xffffffffu, s2, off);
            q2 += __shfl_xor_sync(0xffffffffu, q2, off);
        }
        if (lq == 0) {
            atomicAdd(&d_sum[o1], s1);
            atomicAdd(&d_sumsq[o1], q1);
            atomicAdd(&d_sum[o2], s2);
            atomicAdd(&d_sumsq[o2], q2);
        }
    }
}

// ---------------------------------------------------------------------------
// K6: out = scale[o]*wy16 + shift[o] + x, with BN finalize fused (each block
// spans exactly one channel; stat loads are broadcast).
// ---------------------------------------------------------------------------
__global__ __launch_bounds__(512) void k_out(const float* __restrict__ x,
                                             const float* __restrict__ gamma,
                                             const float* __restrict__ beta,
                                             float* __restrict__ out)
{
    size_t i4 = (size_t)blockIdx.x * 512 + threadIdx.x;   // 4 elements each
    int o = (int)((i4 >> 11) & 255);
    float mean = d_sum[o]   * (1.0f / BNT);
    float var  = d_sumsq[o] * (1.0f / BNT) - mean * mean;
    float sc   = gamma[o] * rsqrtf(var + 1e-5f);
    float sh   = beta[o] - mean * sc;
    const __half2* w2 = (const __half2*)d_wy16;
    float2 f0 = __half22float2(w2[i4 * 2]);
    float2 f1 = __half22float2(w2[i4 * 2 + 1]);
    float4 xv = *((const float4*)x + i4);
    float4 r;
    r.x = fmaf(sc, f0.x, sh) + xv.x;
    r.y = fmaf(sc, f0.y, sh) + xv.y;
    r.z = fmaf(sc, f1.x, sh) + xv.z;
    r.w = fmaf(sc, f1.y, sh) + xv.w;
    ((float4*)out)[i4] = r;
}

// ---------------------------------------------------------------------------
// Launch: fork/join (graph-capturable).
// ---------------------------------------------------------------------------
extern "C" void kernel_launch(void* const* d_in, const int* in_sizes, int n_in,
                              void* d_out, int out_size)
{
    const float* x     = (const float*)d_in[0];
    const float* tw    = (const float*)d_in[1];
    const float* tb    = (const float*)d_in[2];
    const float* pw    = (const float*)d_in[3];
    const float* pb    = (const float*)d_in[4];
    const float* gw    = (const float*)d_in[5];
    const float* gb    = (const float*)d_in[6];
    const float* ww    = (const float*)d_in[7];
    const float* wb    = (const float*)d_in[8];
    const float* gamma = (const float*)d_in[9];
    const float* beta  = (const float*)d_in[10];
    float* out = (float*)d_out;

    static cudaStream_t s1 = nullptr, s2 = nullptr;
    static cudaEvent_t eF = nullptr, eI = nullptr, eX = nullptr, eJ = nullptr;
    static int init_done = 0;
    if (!init_done) {
        cudaFuncSetAttribute(k_conv_th, cudaFuncAttributeMaxDynamicSharedMemorySize, SMEM16);
        cudaFuncSetAttribute(k_conv_pg, cudaFuncAttributeMaxDynamicSharedMemorySize, SMEM16);
        cudaFuncSetAttribute(k_S16,     cudaFuncAttributeMaxDynamicSharedMemorySize, SMEM16);
        cudaFuncSetAttribute(k_wy16,    cudaFuncAttributeMaxDynamicSharedMemorySize, SMEM16);
        int lo, hi;
        cudaDeviceGetStreamPriorityRange(&lo, &hi);
        cudaStreamCreateWithPriority(&s1, cudaStreamNonBlocking, hi);
        cudaStreamCreateWithPriority(&s2, cudaStreamNonBlocking, hi);
        cudaEventCreateWithFlags(&eF, cudaEventDisableTiming);
        cudaEventCreateWithFlags(&eI, cudaEventDisableTiming);
        cudaEventCreateWithFlags(&eX, cudaEventDisableTiming);
        cudaEventCreateWithFlags(&eJ, cudaEventDisableTiming);
        init_done = 1;
    }

    cudaEventRecord(eF, 0);
    cudaStreamWaitEvent(s1, eF, 0);
    cudaStreamWaitEvent(s2, eF, 0);

    // s2: zero accumulators + weight conversion.
    k_init<<<256, 256, 0, s2>>>();
    k_wcvt<<<384, 256, 0, s2>>>(tw, pw, gw);
    cudaEventRecord(eI, s2);

    // s0: transpose+convert x.
    k_xt<<<dim3(TT / 64, CC / 64, BB), 256, 0, 0>>>(x);
    cudaEventRecord(eX, 0);

    // s1: phi+g convs, then S, then M.
    cudaStreamWaitEvent(s1, eX, 0);
    cudaStreamWaitEvent(s1, eI, 0);
    k_conv_pg<<<dim3(TT / 128, 2, BB), 256, SMEM16, s1>>>(pb, gb);
    k_S16<<<dim3(16, BB), 256, SMEM16, s1>>>();
    k_M2f<<<128, 256, 0, s1>>>(ww);
    cudaEventRecord(eJ, s1);

    // s0: theta conv concurrently (after weights are converted).
    cudaStreamWaitEvent(0, eI, 0);
    k_conv_th<<<dim3(TT / 128, 1, BB), 256, SMEM16, 0>>>(tb);

    // Join, then dependent tail (stats fused into k_out).
    cudaStreamWaitEvent(0, eJ, 0);
    k_wy16<<<dim3(TT / 128, 2, BB), 256, SMEM16, 0>>>(wb);
    k_out<<<4096, 512>>>(x, gamma, beta, out);
}

// round 17
// speedup vs baseline: 1.3500x; 1.0499x over previous
#include <cuda_runtime.h>
#include <cuda_fp16.h>
#include <cstdint>

#define BB 4
#define CC 256
#define CI 128
#define TT 8192
#define NN 4096
#define BNT (BB*TT)

// Scratch (device globals; no allocation allowed). 16B-aligned for cp.async.
__device__ __align__(16) __half d_xt16[BB*TT*CC];  // x^T [b][t][c], 16 MB
__device__ __align__(16) __half d_w16[3*CI*CC];    // theta/phi/g weights fp16
__device__ __align__(16) __half d_th16[BB*TT*CI];  // theta^T [b][t][a], 8 MB
__device__ __align__(16) __half d_p16[BB*CI*NN];   // phi [b][ci][n], 4 MB
__device__ __align__(16) __half d_g16[BB*CI*NN];   // g   [b][ci][n], 4 MB
__device__ __align__(16) __half d_M16[BB*CC*CI];   // M [b][o][a] fp16
__device__ __align__(16) __half d_wy16[BB*CC*TT];  // wy fp16, 16 MB
__device__ float d_S[BB*CI*CI];
__device__ float d_sum[CC];
__device__ float d_sumsq[CC];

// ---------------- fp16 mma.sync (m16n8k16), fp32 accumulate -----------------
__device__ __forceinline__ void mma_f16(float* d, const uint32_t* a, const uint32_t* b) {
    asm("mma.sync.aligned.m16n8k16.row.col.f32.f16.f16.f32 "
        "{%0,%1,%2,%3}, {%4,%5,%6,%7}, {%8,%9}, {%0,%1,%2,%3};"
        : "+f"(d[0]), "+f"(d[1]), "+f"(d[2]), "+f"(d[3])
        : "r"(a[0]), "r"(a[1]), "r"(a[2]), "r"(a[3]), "r"(b[0]), "r"(b[1]));
}
// ldmatrix x4: four 8x8 b16 tiles, one address per lane.
__device__ __forceinline__ void ldsm4(uint32_t* r, uint32_t addr) {
    asm volatile("ldmatrix.sync.aligned.m8n8.x4.shared.b16 {%0,%1,%2,%3}, [%4];"
        : "=r"(r[0]), "=r"(r[1]), "=r"(r[2]), "=r"(r[3]) : "r"(addr));
}

// ---------------- cp.async helpers ------------------------------------------
__device__ __forceinline__ uint32_t smem_u32(const void* p) {
    uint32_t a;
    asm("{ .reg .u64 t; cvta.to.shared.u64 t, %1; cvt.u32.u64 %0, t; }" : "=r"(a) : "l"(p));
    return a;
}
__device__ __forceinline__ void cp16(uint32_t dst, const void* src) {
    asm volatile("cp.async.cg.shared.global [%0], [%1], 16;" :: "r"(dst), "l"(src));
}
#define CP_COMMIT() asm volatile("cp.async.commit_group;" ::: "memory")
#define CP_WAIT1()  asm volatile("cp.async.wait_group 1;" ::: "memory")
#define CP_WAIT0()  asm volatile("cp.async.wait_group 0;" ::: "memory")

// SMEM: per stage two fp16 tiles, 128 rows x 64 halves (32 u32), pitch 36 u32
// (144 B = 9 x 16B: the 8 rows of each LDSM phase hit distinct 16B banks).
#define PIT 36
#define TSZ (128*PIT)          // 4608 u32 per tile
#define STGH (2*TSZ)           // 9216 u32 per stage
#define SMEM16 (2*STGH*4)      // 73728 B

// Stage 128 rows x 64 halves from row-major fp16 src (ld = lds halves).
__device__ __forceinline__ void stage_h(uint32_t dstb, const __half* __restrict__ src,
                                        int lds, int koff, int tid) {
#pragma unroll
    for (int i = 0; i < 4; i++) {
        int fid = i * 256 + tid;        // 0..1023 16B-chunks
        int r = fid >> 3, q = fid & 7;
        cp16(dstb + (uint32_t)(r * PIT + q * 4) * 4,
             src + (size_t)r * lds + koff + q * 8);
    }
}

// ---------------------------------------------------------------------------
// Shared HMMA mainloop (per-SMSP k-step rotation).
// ---------------------------------------------------------------------------
__device__ __forceinline__ void hmma_loop(
    float acc[2][8][4], uint32_t smb,
    const __half* __restrict__ Asrc, int lda,
    const __half* __restrict__ Bsrc, int ldb,
    int NC, int tid)
{
    const int lane = tid & 31;
    const int warp = tid >> 5;
    const int wo = warp >> 1, wt = warp & 1;
    const uint32_t aoff =
        ((uint32_t)(((lane & 7) + ((lane >> 3) & 1) * 8) * PIT + (lane >> 4) * 4)) * 4;
    const uint32_t boff =
        ((uint32_t)(((lane >> 4) * 8 + (lane & 7)) * PIT + ((lane >> 3) & 1) * 4)) * 4;

    stage_h(smb, Asrc, lda, 0, tid);
    stage_h(smb + TSZ * 4, Bsrc, ldb, 0, tid);
    CP_COMMIT();

    for (int kc = 0; kc < NC; kc++) {
        if (kc + 1 < NC) {
            uint32_t ab = smb + (uint32_t)(((kc + 1) & 1) * STGH) * 4;
            stage_h(ab, Asrc, lda, (kc + 1) * 64, tid);
            stage_h(ab + TSZ * 4, Bsrc, ldb, (kc + 1) * 64, tid);
            CP_COMMIT();
            CP_WAIT1();
        } else {
            CP_WAIT0();
        }
        __syncthreads();
        const uint32_t As_b = smb + (uint32_t)((kc & 1) * STGH) * 4;
        const uint32_t Bs_b = As_b + TSZ * 4;
#pragma unroll
        for (int ks = 0; ks < 4; ks++) {
            int kss = (ks + wo) & 3;            // per-SMSP-partner rotation
            uint32_t k04 = (uint32_t)kss * 32;  // 8 u32 per ks
            uint32_t a[2][4], bf[4][4];
            ldsm4(a[0], As_b + (uint32_t)((wo * 2 + 0) * 16 * PIT) * 4 + k04 + aoff);
            ldsm4(a[1], As_b + (uint32_t)((wo * 2 + 1) * 16 * PIT) * 4 + k04 + aoff);
#pragma unroll
            for (int j = 0; j < 4; j++)
                ldsm4(bf[j], Bs_b + (uint32_t)((wt * 64 + j * 16) * PIT) * 4 + k04 + boff);
#pragma unroll
            for (int mi = 0; mi < 2; mi++)
#pragma unroll
                for (int j = 0; j < 4; j++) {
                    mma_f16(acc[mi][2 * j],     a[mi], &bf[j][0]);
                    mma_f16(acc[mi][2 * j + 1], a[mi], &bf[j][2]);
                }
        }
        __syncthreads();
    }
}

// ---------------------------------------------------------------------------
// K0: zero accumulators AND convert weights (merged; grid 384 x 256).
// ---------------------------------------------------------------------------
__global__ void k_initcvt(const float* __restrict__ tw, const float* __restrict__ pw,
                          const float* __restrict__ gw) {
    int i = blockIdx.x * 256 + threadIdx.x;          // 0..98303
    const float* src = (i < CI*CC) ? tw : ((i < 2*CI*CC) ? pw : gw);
    d_w16[i] = __float2half(src[i & (CI*CC - 1)]);
    if (i < BB*CI*CI) d_S[i] = 0.0f;
    if (i < CC) { d_sum[i] = 0.0f; d_sumsq[i] = 0.0f; }
}

// Transpose+convert x [b][c][t] fp32 -> d_xt16 [b][t][c] fp16. 64x64 tiles.
// t_base selects the half being processed.
__global__ __launch_bounds__(256) void k_xt(const float* __restrict__ x, int t_base) {
    __shared__ float sm[64][65];
    const int b = blockIdx.z, c0 = blockIdx.y * 64, t0 = t_base + blockIdx.x * 64;
    const float* xb = x + ((size_t)b * CC + c0) * TT + t0;
    const int tid = threadIdx.x;
#pragma unroll
    for (int i = 0; i < 4; i++) {
        int id = i * 256 + tid;
        int c = id >> 4, t4 = (id & 15) * 4;
        float4 v = *(const float4*)(xb + (size_t)c * TT + t4);
        sm[c][t4] = v.x; sm[c][t4+1] = v.y; sm[c][t4+2] = v.z; sm[c][t4+3] = v.w;
    }
    __syncthreads();
    __half* dst = d_xt16 + ((size_t)b * TT + t0) * CC + c0;
#pragma unroll
    for (int i = 0; i < 8; i++) {
        int id = i * 256 + tid;
        int t = id >> 5, cp = id & 31;
        *(__half2*)(dst + (size_t)t * CC + 2 * cp) =
            __floats2half2_rn(sm[2*cp][t], sm[2*cp+1][t]);
    }
}

// ---------------------------------------------------------------------------
// K1a: theta conv. A = x^T tile (M=t), B = W_theta (N=o). Output theta^T fp16.
// ---------------------------------------------------------------------------
__global__ void __launch_bounds__(256, 2) k_conv_th(const float* __restrict__ bt,
                                                    int t_base)
{
    extern __shared__ uint32_t smem[];
    const uint32_t smb = smem_u32(smem);
    const int tid = threadIdx.x;
    const int warp = tid >> 5, lane = tid & 31;
    const int wo = warp >> 1, wt = warp & 1;
    const int b  = blockIdx.z;
    const int t0 = t_base + blockIdx.x * 128;

    float acc[2][8][4];
#pragma unroll
    for (int mi = 0; mi < 2; mi++)
#pragma unroll
        for (int nt = 0; nt < 8; nt++)
#pragma unroll
            for (int j = 0; j < 4; j++) acc[mi][nt][j] = 0.0f;

    hmma_loop(acc, smb, d_xt16 + ((size_t)b * TT + t0) * CC, CC, d_w16, CC, 4, tid);

    const int lq = lane & 3, lr = lane >> 2;
    __half* dst = d_th16 + ((size_t)b * TT + t0) * CI;
#pragma unroll
    for (int mi = 0; mi < 2; mi++) {
        int t1 = wo * 32 + mi * 16 + lr;
        int t2 = t1 + 8;
#pragma unroll
        for (int nt = 0; nt < 8; nt++) {
            int o = wt * 64 + nt * 8 + 2 * lq;
            float b0 = bt[o], b1 = bt[o + 1];
            *(__half2*)(dst + (size_t)t1 * CI + o) =
                __floats2half2_rn(acc[mi][nt][0] + b0, acc[mi][nt][1] + b1);
            *(__half2*)(dst + (size_t)t2 * CI + o) =
                __floats2half2_rn(acc[mi][nt][2] + b0, acc[mi][nt][3] + b1);
        }
    }
}

// ---------------------------------------------------------------------------
// K1b: phi/g conv (blockIdx.y selects). A = W (M=o), B = x^T (N=t); maxpool
// over in-thread t-pair. Output fp16 [ci][n].
// ---------------------------------------------------------------------------
__global__ void __launch_bounds__(256, 2) k_conv_pg(const float* __restrict__ pb,
                                                    const float* __restrict__ gb,
                                                    int t_base)
{
    extern __shared__ uint32_t smem[];
    const uint32_t smb = smem_u32(smem);
    const int tid = threadIdx.x;
    const int warp = tid >> 5, lane = tid & 31;
    const int wo = warp >> 1, wt = warp & 1;
    const int b  = blockIdx.z;
    const int w  = blockIdx.y;               // 0 = phi, 1 = g
    const int t0 = t_base + blockIdx.x * 128;
    const float* bias = (w == 0) ? pb : gb;

    float acc[2][8][4];
#pragma unroll
    for (int mi = 0; mi < 2; mi++)
#pragma unroll
        for (int nt = 0; nt < 8; nt++)
#pragma unroll
            for (int j = 0; j < 4; j++) acc[mi][nt][j] = 0.0f;

    hmma_loop(acc, smb, d_w16 + (size_t)(1 + w) * CI * CC, CC,
              d_xt16 + ((size_t)b * TT + t0) * CC, CC, 4, tid);

    const int lq = lane & 3, lr = lane >> 2;
    __half* dst = ((w == 0) ? d_p16 : d_g16) + (size_t)b * CI * NN + (t0 >> 1);
#pragma unroll
    for (int mi = 0; mi < 2; mi++) {
        int o1 = wo * 32 + mi * 16 + lr;
        int o2 = o1 + 8;
        float bz1 = bias[o1], bz2 = bias[o2];
#pragma unroll
        for (int nt = 0; nt < 8; nt++) {
            int np = wt * 32 + nt * 4 + lq;
            dst[(size_t)o1 * NN + np] =
                __float2half(fmaxf(acc[mi][nt][0], acc[mi][nt][1]) + bz1);
            dst[(size_t)o2 * NN + np] =
                __float2half(fmaxf(acc[mi][nt][2], acc[mi][nt][3]) + bz2);
        }
    }
}

// ---------------------------------------------------------------------------
// K2: S = phi . g^T. Split-K: 32 slabs of 128 n (2 chunks). fp32 atomics.
// ---------------------------------------------------------------------------
__global__ void __launch_bounds__(256, 2) k_S16()
{
    extern __shared__ uint32_t smem[];
    const uint32_t smb = smem_u32(smem);
    const int tid = threadIdx.x;
    const int warp = tid >> 5, lane = tid & 31;
    const int wo = warp >> 1, wt = warp & 1;
    const int b  = blockIdx.y;
    const int n0 = blockIdx.x * 128;

    float acc[2][8][4];
#pragma unroll
    for (int mi = 0; mi < 2; mi++)
#pragma unroll
        for (int nt = 0; nt < 8; nt++)
#pragma unroll
            for (int j = 0; j < 4; j++) acc[mi][nt][j] = 0.0f;

    hmma_loop(acc, smb, d_p16 + (size_t)b * CI * NN + n0, NN,
              d_g16 + (size_t)b * CI * NN + n0, NN, 2, tid);

    const int lq = lane & 3, lr = lane >> 2;
    float* Sp = d_S + (size_t)b * CI * CI;
#pragma unroll
    for (int mi = 0; mi < 2; mi++) {
        int a1 = wo * 32 + mi * 16 + lr;
        int a2 = a1 + 8;
#pragma unroll
        for (int nt = 0; nt < 8; nt++) {
            int ci = wt * 64 + nt * 8 + 2 * lq;
            atomicAdd(&Sp[(size_t)a1 * CI + ci],     acc[mi][nt][0]);
            atomicAdd(&Sp[(size_t)a1 * CI + ci + 1], acc[mi][nt][1]);
            atomicAdd(&Sp[(size_t)a2 * CI + ci],     acc[mi][nt][2]);
            atomicAdd(&Sp[(size_t)a2 * CI + ci + 1], acc[mi][nt][3]);
        }
    }
}

// ---------------------------------------------------------------------------
// K3: M[b,o,a] = (1/N) sum_k ww[o,k] S[b,a,k]; fp32 SIMT, writes fp16 M.
// ---------------------------------------------------------------------------
__global__ __launch_bounds__(256) void k_M2f(const float* __restrict__ ww)
{
    __shared__ float ws[32][129];
    __shared__ float ss[32][129];

    const int tid = threadIdx.x;
    const int b  = blockIdx.x >> 5;
    const int ob = (blockIdx.x >> 2) & 7;
    const int ab = blockIdx.x & 3;

#pragma unroll
    for (int i = 0; i < 4; i++) {
        int fid = i * 256 + tid;
        int r = fid >> 5, c4 = fid & 31;
        float4 v = *(const float4*)(ww + (size_t)(ob * 32 + r) * CI + 4 * c4);
        ws[r][4*c4+0] = v.x; ws[r][4*c4+1] = v.y; ws[r][4*c4+2] = v.z; ws[r][4*c4+3] = v.w;
        float4 u = *(const float4*)(d_S + (size_t)b * CI * CI + (size_t)(ab * 32 + r) * CI + 4 * c4);
        ss[r][4*c4+0] = u.x; ss[r][4*c4+1] = u.y; ss[r][4*c4+2] = u.z; ss[r][4*c4+3] = u.w;
    }
    __syncthreads();

    const int ty = tid >> 3;
    const int tx = tid & 7;
    float acc[4] = {0.f, 0.f, 0.f, 0.f};
#pragma unroll
    for (int k = 0; k < CI; k++) {
        float wv = ws[ty][k];
#pragma unroll
        for (int j = 0; j < 4; j++) acc[j] = fmaf(wv, ss[4*tx+j][k], acc[j]);
    }
    const float invN = 1.0f / NN;
    __half* Mp = d_M16 + (size_t)b * CC * CI + (size_t)(ob * 32 + ty) * CI + ab * 32 + 4 * tx;
#pragma unroll
    for (int j = 0; j < 4; j++) Mp[j] = __float2half(acc[j] * invN);
}

// ---------------------------------------------------------------------------
// K4: wy = M16 . theta^T + w_b (fp16 mma); writes fp16 wy; BN sums from the
// ROUNDED values so stats match exactly what k_out scales.
// ---------------------------------------------------------------------------
__global__ void __launch_bounds__(256, 2) k_wy16(const float* __restrict__ wb)
{
    extern __shared__ uint32_t smem[];
    const uint32_t smb = smem_u32(smem);
    const int tid = threadIdx.x;
    const int warp = tid >> 5, lane = tid & 31;
    const int wo = warp >> 1, wt = warp & 1;
    const int b  = blockIdx.z;
    const int o0 = blockIdx.y * 128;
    const int t0 = blockIdx.x * 128;

    float acc[2][8][4];
#pragma unroll
    for (int mi = 0; mi < 2; mi++)
#pragma unroll
        for (int nt = 0; nt < 8; nt++)
#pragma unroll
            for (int j = 0; j < 4; j++) acc[mi][nt][j] = 0.0f;

    hmma_loop(acc, smb, d_M16 + ((size_t)b * CC + o0) * CI, CI,
              d_th16 + ((size_t)b * TT + t0) * CI, CI, 2, tid);

    const int lq = lane & 3, lr = lane >> 2;
    __half* wyp = d_wy16 + (size_t)b * CC * TT;
#pragma unroll
    for (int mi = 0; mi < 2; mi++) {
        int o1 = o0 + wo * 32 + mi * 16 + lr;
        int o2 = o1 + 8;
        float bz1 = wb[o1], bz2 = wb[o2];
        float s1 = 0.f, q1 = 0.f, s2 = 0.f, q2 = 0.f;
#pragma unroll
        for (int nt = 0; nt < 8; nt++) {
            int t = t0 + wt * 64 + nt * 8 + 2 * lq;
            __half2 h1 = __floats2half2_rn(acc[mi][nt][0] + bz1, acc[mi][nt][1] + bz1);
            __half2 h2 = __floats2half2_rn(acc[mi][nt][2] + bz2, acc[mi][nt][3] + bz2);
            *(__half2*)(wyp + (size_t)o1 * TT + t) = h1;
            *(__half2*)(wyp + (size_t)o2 * TT + t) = h2;
            float2 f1 = __half22float2(h1), f2 = __half22float2(h2);
            s1 += f1.x + f1.y; q1 = fmaf(f1.x, f1.x, q1); q1 = fmaf(f1.y, f1.y, q1);
            s2 += f2.x + f2.y; q2 = fmaf(f2.x, f2.x, q2); q2 = fmaf(f2.y, f2.y, q2);
        }
#pragma unroll
        for (int off = 1; off < 4; off <<= 1) {
            s1 += __shfl_xor_sync(0xffffffffu, s1, off);
            q1 += __shfl_xor_sync(0xffffffffu, q1, off);
            s2 += __shfl_xor_sync(0xffffffffu, s2, off);
            q2 += __shfl_xor_sync(0xffffffffu, q2, off);
        }
        if (lq == 0) {
            atomicAdd(&d_sum[o1], s1);
            atomicAdd(&d_sumsq[o1], q1);
            atomicAdd(&d_sum[o2], s2);
            atomicAdd(&d_sumsq[o2], q2);
        }
    }
}

// ---------------------------------------------------------------------------
// K6: out = scale[o]*wy16 + shift[o] + x, BN finalize fused (per-channel
// blocks; stat loads are broadcast).
// ---------------------------------------------------------------------------
__global__ __launch_bounds__(512) void k_out(const float* __restrict__ x,
                                             const float* __restrict__ gamma,
                                             const float* __restrict__ beta,
                                             float* __restrict__ out)
{
    size_t i4 = (size_t)blockIdx.x * 512 + threadIdx.x;   // 4 elements each
    int o = (int)((i4 >> 11) & 255);
    float mean = d_sum[o]   * (1.0f / BNT);
    float var  = d_sumsq[o] * (1.0f / BNT) - mean * mean;
    float sc   = gamma[o] * rsqrtf(var + 1e-5f);
    float sh   = beta[o] - mean * sc;
    const __half2* w2 = (const __half2*)d_wy16;
    float2 f0 = __half22float2(w2[i4 * 2]);
    float2 f1 = __half22float2(w2[i4 * 2 + 1]);
    float4 xv = *((const float4*)x + i4);
    float4 r;
    r.x = fmaf(sc, f0.x, sh) + xv.x;
    r.y = fmaf(sc, f0.y, sh) + xv.y;
    r.z = fmaf(sc, f1.x, sh) + xv.z;
    r.w = fmaf(sc, f1.y, sh) + xv.w;
    ((float4*)out)[i4] = r;
}

// ---------------------------------------------------------------------------
// Launch: fork/join, xt pipelined in t-halves (graph-capturable).
//   s2: initcvt -> eI
//   s0: xt(half0) -> eX0 ; xt(half1) -> eX1 ; [eI] conv_th(h0) ; conv_th(h1)
//   s1: [eX0,eI] conv_pg(h0) ; [eX1] conv_pg(h1) ; S ; M -> eJ
//   s0 tail: [eJ] wy -> out
// ---------------------------------------------------------------------------
extern "C" void kernel_launch(void* const* d_in, const int* in_sizes, int n_in,
                              void* d_out, int out_size)
{
    const float* x     = (const float*)d_in[0];
    const float* tw    = (const float*)d_in[1];
    const float* tb    = (const float*)d_in[2];
    const float* pw    = (const float*)d_in[3];
    const float* pb    = (const float*)d_in[4];
    const float* gw    = (const float*)d_in[5];
    const float* gb    = (const float*)d_in[6];
    const float* ww    = (const float*)d_in[7];
    const float* wb    = (const float*)d_in[8];
    const float* gamma = (const float*)d_in[9];
    const float* beta  = (const float*)d_in[10];
    float* out = (float*)d_out;

    static cudaStream_t s1 = nullptr, s2 = nullptr;
    static cudaEvent_t eF = nullptr, eI = nullptr, eX0 = nullptr, eX1 = nullptr,
                       eJ = nullptr;
    static int init_done = 0;
    if (!init_done) {
        cudaFuncSetAttribute(k_conv_th, cudaFuncAttributeMaxDynamicSharedMemorySize, SMEM16);
        cudaFuncSetAttribute(k_conv_pg, cudaFuncAttributeMaxDynamicSharedMemorySize, SMEM16);
        cudaFuncSetAttribute(k_S16,     cudaFuncAttributeMaxDynamicSharedMemorySize, SMEM16);
        cudaFuncSetAttribute(k_wy16,    cudaFuncAttributeMaxDynamicSharedMemorySize, SMEM16);
        int lo, hi;
        cudaDeviceGetStreamPriorityRange(&lo, &hi);
        cudaStreamCreateWithPriority(&s1, cudaStreamNonBlocking, hi);
        cudaStreamCreateWithPriority(&s2, cudaStreamNonBlocking, hi);
        cudaEventCreateWithFlags(&eF,  cudaEventDisableTiming);
        cudaEventCreateWithFlags(&eI,  cudaEventDisableTiming);
        cudaEventCreateWithFlags(&eX0, cudaEventDisableTiming);
        cudaEventCreateWithFlags(&eX1, cudaEventDisableTiming);
        cudaEventCreateWithFlags(&eJ,  cudaEventDisableTiming);
        init_done = 1;
    }

    cudaEventRecord(eF, 0);
    cudaStreamWaitEvent(s1, eF, 0);
    cudaStreamWaitEvent(s2, eF, 0);

    // s2: zero accumulators + weight conversion (one kernel).
    k_initcvt<<<384, 256, 0, s2>>>(tw, pw, gw);
    cudaEventRecord(eI, s2);

    // s0: transpose+convert x in two t-halves.
    k_xt<<<dim3(TT / 128, CC / 64, BB), 256, 0, 0>>>(x, 0);
    cudaEventRecord(eX0, 0);
    k_xt<<<dim3(TT / 128, CC / 64, BB), 256, 0, 0>>>(x, TT / 2);
    cudaEventRecord(eX1, 0);

    // s1: phi+g convs (pipelined halves), then S, then M.
    cudaStreamWaitEvent(s1, eX0, 0);
    cudaStreamWaitEvent(s1, eI, 0);
    k_conv_pg<<<dim3(TT / 256, 2, BB), 256, SMEM16, s1>>>(pb, gb, 0);
    cudaStreamWaitEvent(s1, eX1, 0);
    k_conv_pg<<<dim3(TT / 256, 2, BB), 256, SMEM16, s1>>>(pb, gb, TT / 2);
    k_S16<<<dim3(32, BB), 256, SMEM16, s1>>>();
    k_M2f<<<128, 256, 0, s1>>>(ww);
    cudaEventRecord(eJ, s1);

    // s0: theta conv concurrently (after weights converted; xt order on s0).
    cudaStreamWaitEvent(0, eI, 0);
    k_conv_th<<<dim3(TT / 256, 1, BB), 256, SMEM16, 0>>>(tb, 0);
    k_conv_th<<<dim3(TT / 256, 1, BB), 256, SMEM16, 0>>>(tb, TT / 2);

    // Join, then dependent tail (stats fused into k_out).
    cudaStreamWaitEvent(0, eJ, 0);
    k_wy16<<<dim3(TT / 128, 2, BB), 256, SMEM16, 0>>>(wb);
    k_out<<<4096, 512>>>(x, gamma, beta, out);
}